// round 2
// baseline (speedup 1.0000x reference)
#include <cuda_runtime.h>
#include <math.h>

#define kS  1024
#define kB  4
#define kD  1024
#define kH  16
#define kDH 64

// Scratch (static device globals; no dynamic allocation allowed)
__device__ float g_q[kB*kH*kS*kDH];   // [b][h][s][dh]
__device__ float g_k[kB*kH*kS*kDH];
__device__ float g_v[kB*kH*kS*kDH];
__device__ float g_o[kS*kB*kH*kDH];   // [s][b][h*DH+dh] (concat layout for final GEMM)

// ---------------------------------------------------------------------------
// Kernel 1: per-head projection  out[b,h,s,:] = act[s,b,:] @ W[h,:,:] + bias[h,:]
// BM=128 rows of s, BN=64 (=DH), BK=16. 256 threads, 8x4 register tile.
// ---------------------------------------------------------------------------
__global__ void __launch_bounds__(256) proj_kernel(
    const float* __restrict__ act,   // [S, B, D]
    const float* __restrict__ W,     // [H, D, DH]
    const float* __restrict__ bias,  // [H, DH]
    int which)                       // 0->g_q, 1->g_k, 2->g_v
{
    float* out = (which == 0) ? g_q : (which == 1) ? g_k : g_v;
    int s0 = blockIdx.x * 128;
    int h  = blockIdx.y;
    int b  = blockIdx.z;

    __shared__ float As[16][128];
    __shared__ float Bs[16][64];

    int tid = threadIdx.x;
    int ty = tid >> 4, tx = tid & 15;

    float acc[8][4];
    #pragma unroll
    for (int i = 0; i < 8; i++)
        #pragma unroll
        for (int j = 0; j < 4; j++) acc[i][j] = 0.f;

    for (int k0 = 0; k0 < kD; k0 += 16) {
        #pragma unroll
        for (int i = 0; i < 2; i++) {
            int idx = tid + i * 256;          // 0..511
            int m  = idx >> 2;                // 0..127
            int k4 = (idx & 3) * 4;           // 0,4,8,12
            float4 va = *(const float4*)(act + ((size_t)(s0 + m) * kB + b) * kD + k0 + k4);
            As[k4 + 0][m] = va.x; As[k4 + 1][m] = va.y;
            As[k4 + 2][m] = va.z; As[k4 + 3][m] = va.w;
        }
        {
            int kk = tid >> 4;                // 0..15
            int n4 = (tid & 15) * 4;          // 0..60
            *(float4*)&Bs[kk][n4] = *(const float4*)(W + ((size_t)h * kD + k0 + kk) * kDH + n4);
        }
        __syncthreads();

        #pragma unroll
        for (int kk = 0; kk < 16; kk++) {
            float4 a0 = *(const float4*)&As[kk][ty * 8];
            float4 a1 = *(const float4*)&As[kk][ty * 8 + 4];
            float a[8] = {a0.x, a0.y, a0.z, a0.w, a1.x, a1.y, a1.z, a1.w};
            float4 b4 = *(const float4*)&Bs[kk][tx * 4];
            #pragma unroll
            for (int i = 0; i < 8; i++) {
                acc[i][0] += a[i] * b4.x;
                acc[i][1] += a[i] * b4.y;
                acc[i][2] += a[i] * b4.z;
                acc[i][3] += a[i] * b4.w;
            }
        }
        __syncthreads();
    }

    float4 bv = *(const float4*)(bias + h * kDH + tx * 4);
    #pragma unroll
    for (int i = 0; i < 8; i++) {
        float4 o;
        o.x = acc[i][0] + bv.x; o.y = acc[i][1] + bv.y;
        o.z = acc[i][2] + bv.z; o.w = acc[i][3] + bv.w;
        *(float4*)(out + (((size_t)b * kH + h) * kS + s0 + ty * 8 + i) * kDH + tx * 4) = o;
    }
}

// ---------------------------------------------------------------------------
// Kernel 2: flash attention per (b,h). 64 query rows per block, 64-key tiles.
// 256 threads = 8 warps; warp w owns query rows w*8..w*8+7, lane owns score/O
// columns (lane, lane+32). Online softmax kept warp-local.
// ---------------------------------------------------------------------------
__global__ void __launch_bounds__(256) attn_kernel(const int* __restrict__ mask)
{
    extern __shared__ float smf[];
    float* Qs = smf;                  // [64][64]
    float* Ks = Qs + 64 * 64;         // [64][68]  padded: conflict-free LDS.128
    float* Ps = Ks + 64 * 68;         // [64][68]
    float* Vs = Ps + 64 * 68;         // [64][64]
    float* Mk = Vs + 64 * 64;         // [64]

    int s0 = blockIdx.x * 64;
    int h  = blockIdx.y;
    int b  = blockIdx.z;
    int tid  = threadIdx.x;
    int warp = tid >> 5, lane = tid & 31;

    const size_t base = ((size_t)b * kH + h) * kS * kDH;
    const float* qb = g_q + base;
    const float* kb = g_k + base;
    const float* vb = g_v + base;

    #pragma unroll
    for (int i = 0; i < 4; i++) {
        int idx = tid + i * 256;
        int r = idx >> 4, k4 = (idx & 15) * 4;
        *(float4*)&Qs[r * 64 + k4] = *(const float4*)(qb + (size_t)(s0 + r) * kDH + k4);
    }

    int r0 = warp * 8;
    int d0 = lane, d1 = lane + 32;
    float m_run[8], l_run[8], o0[8], o1[8];
    #pragma unroll
    for (int r = 0; r < 8; r++) { m_run[r] = -INFINITY; l_run[r] = 0.f; o0[r] = 0.f; o1[r] = 0.f; }

    const float scale = 0.125f;  // 1/sqrt(64)

    for (int j0 = 0; j0 < kS; j0 += 64) {
        __syncthreads();  // prior-tile smem reads done before overwrite
        #pragma unroll
        for (int i = 0; i < 4; i++) {
            int idx = tid + i * 256;
            int c = idx >> 4, k4 = (idx & 15) * 4;
            *(float4*)&Ks[c * 68 + k4] = *(const float4*)(kb + (size_t)(j0 + c) * kDH + k4);
            *(float4*)&Vs[c * 64 + k4] = *(const float4*)(vb + (size_t)(j0 + c) * kDH + k4);
        }
        if (tid < 64) Mk[tid] = (float)mask[(size_t)(j0 + tid) * kB + b] * 1e18f;
        __syncthreads();

        // ---- scores: S = Q @ K^T ----
        float acc0[8], acc1[8];
        #pragma unroll
        for (int r = 0; r < 8; r++) { acc0[r] = 0.f; acc1[r] = 0.f; }
        #pragma unroll
        for (int k4 = 0; k4 < 64; k4 += 4) {
            float4 kc0 = *(const float4*)&Ks[d0 * 68 + k4];
            float4 kc1 = *(const float4*)&Ks[d1 * 68 + k4];
            #pragma unroll
            for (int r = 0; r < 8; r++) {
                float4 q = *(const float4*)&Qs[(r0 + r) * 64 + k4];
                acc0[r] += q.x * kc0.x + q.y * kc0.y + q.z * kc0.z + q.w * kc0.w;
                acc1[r] += q.x * kc1.x + q.y * kc1.y + q.z * kc1.z + q.w * kc1.w;
            }
        }

        // ---- online softmax (per warp-owned rows) ----
        float mk0 = Mk[d0], mk1 = Mk[d1];
        #pragma unroll
        for (int r = 0; r < 8; r++) {
            float sv0 = acc0[r] * scale - mk0;
            float sv1 = acc1[r] * scale - mk1;
            float mx = fmaxf(sv0, sv1);
            #pragma unroll
            for (int off = 16; off > 0; off >>= 1)
                mx = fmaxf(mx, __shfl_xor_sync(0xffffffffu, mx, off));
            float m_new = fmaxf(m_run[r], mx);
            float alpha = __expf(m_run[r] - m_new);
            float p0 = __expf(sv0 - m_new);
            float p1 = __expf(sv1 - m_new);
            float ps = p0 + p1;
            #pragma unroll
            for (int off = 16; off > 0; off >>= 1)
                ps += __shfl_xor_sync(0xffffffffu, ps, off);
            l_run[r] = l_run[r] * alpha + ps;
            m_run[r] = m_new;
            o0[r] *= alpha; o1[r] *= alpha;
            Ps[(r0 + r) * 68 + d0] = p0;
            Ps[(r0 + r) * 68 + d1] = p1;
        }
        __syncwarp();

        // ---- O += P @ V ----
        #pragma unroll
        for (int c4 = 0; c4 < 64; c4 += 4) {
            float v00 = Vs[(c4 + 0) * 64 + d0], v01 = Vs[(c4 + 0) * 64 + d1];
            float v10 = Vs[(c4 + 1) * 64 + d0], v11 = Vs[(c4 + 1) * 64 + d1];
            float v20 = Vs[(c4 + 2) * 64 + d0], v21 = Vs[(c4 + 2) * 64 + d1];
            float v30 = Vs[(c4 + 3) * 64 + d0], v31 = Vs[(c4 + 3) * 64 + d1];
            #pragma unroll
            for (int r = 0; r < 8; r++) {
                float4 p = *(const float4*)&Ps[(r0 + r) * 68 + c4];
                o0[r] += p.x * v00 + p.y * v10 + p.z * v20 + p.w * v30;
                o1[r] += p.x * v01 + p.y * v11 + p.z * v21 + p.w * v31;
            }
        }
    }

    #pragma unroll
    for (int r = 0; r < 8; r++) {
        float inv = 1.0f / l_run[r];
        size_t row = ((size_t)(s0 + r0 + r) * kB + b) * (kH * kDH) + (size_t)h * kDH;
        g_o[row + d0] = o0[r] * inv;
        g_o[row + d1] = o1[r] * inv;
    }
}

// ---------------------------------------------------------------------------
// Kernel 3: output projection  out[4096,1024] = g_o[4096,1024] @ Wo + bo
// Same BM=128/BN=64/BK=16 tiling.
// ---------------------------------------------------------------------------
__global__ void __launch_bounds__(256) outproj_kernel(
    const float* __restrict__ Wo,   // [1024, 1024]
    const float* __restrict__ bo,   // [1024]
    float* __restrict__ out)        // [S*B, 1024]
{
    int r0 = blockIdx.x * 128;
    int n0 = blockIdx.y * 64;

    __shared__ float As[16][128];
    __shared__ float Bs[16][64];

    int tid = threadIdx.x;
    int ty = tid >> 4, tx = tid & 15;

    float acc[8][4];
    #pragma unroll
    for (int i = 0; i < 8; i++)
        #pragma unroll
        for (int j = 0; j < 4; j++) acc[i][j] = 0.f;

    for (int k0 = 0; k0 < kH * kDH; k0 += 16) {
        #pragma unroll
        for (int i = 0; i < 2; i++) {
            int idx = tid + i * 256;
            int m  = idx >> 2;
            int k4 = (idx & 3) * 4;
            float4 va = *(const float4*)(g_o + (size_t)(r0 + m) * (kH * kDH) + k0 + k4);
            As[k4 + 0][m] = va.x; As[k4 + 1][m] = va.y;
            As[k4 + 2][m] = va.z; As[k4 + 3][m] = va.w;
        }
        {
            int kk = tid >> 4;
            int n4 = (tid & 15) * 4;
            *(float4*)&Bs[kk][n4] = *(const float4*)(Wo + (size_t)(k0 + kk) * kD + n0 + n4);
        }
        __syncthreads();

        #pragma unroll
        for (int kk = 0; kk < 16; kk++) {
            float4 a0 = *(const float4*)&As[kk][ty * 8];
            float4 a1 = *(const float4*)&As[kk][ty * 8 + 4];
            float a[8] = {a0.x, a0.y, a0.z, a0.w, a1.x, a1.y, a1.z, a1.w};
            float4 b4 = *(const float4*)&Bs[kk][tx * 4];
            #pragma unroll
            for (int i = 0; i < 8; i++) {
                acc[i][0] += a[i] * b4.x;
                acc[i][1] += a[i] * b4.y;
                acc[i][2] += a[i] * b4.z;
                acc[i][3] += a[i] * b4.w;
            }
        }
        __syncthreads();
    }

    float4 bv = *(const float4*)(bo + n0 + tx * 4);
    #pragma unroll
    for (int i = 0; i < 8; i++) {
        float4 o;
        o.x = acc[i][0] + bv.x; o.y = acc[i][1] + bv.y;
        o.z = acc[i][2] + bv.z; o.w = acc[i][3] + bv.w;
        *(float4*)(out + (size_t)(r0 + ty * 8 + i) * kD + n0 + tx * 4) = o;
    }
}

// ---------------------------------------------------------------------------
extern "C" void kernel_launch(void* const* d_in, const int* in_sizes, int n_in,
                              void* d_out, int out_size) {
    (void)in_sizes; (void)n_in; (void)out_size;
    const float* query = (const float*)d_in[0];
    const float* key   = (const float*)d_in[1];
    const float* value = (const float*)d_in[2];
    const int*   kmask = (const int*)  d_in[3];
    const float* Wq    = (const float*)d_in[4];
    const float* bq    = (const float*)d_in[5];
    const float* Wk    = (const float*)d_in[6];
    const float* bk    = (const float*)d_in[7];
    const float* Wv    = (const float*)d_in[8];
    const float* bvp   = (const float*)d_in[9];
    const float* Wo    = (const float*)d_in[10];
    const float* bo    = (const float*)d_in[11];
    float* out = (float*)d_out;

    dim3 pg(kS / 128, kH, kB);
    proj_kernel<<<pg, 256>>>(query, Wq, bq, 0);
    proj_kernel<<<pg, 256>>>(key,   Wk, bk, 1);
    proj_kernel<<<pg, 256>>>(value, Wv, bvp, 2);

    int attn_smem = (64 * 64 + 64 * 68 + 64 * 68 + 64 * 64 + 64) * (int)sizeof(float);
    cudaFuncSetAttribute(attn_kernel, cudaFuncAttributeMaxDynamicSharedMemorySize, attn_smem);
    attn_kernel<<<dim3(kS / 64, kH, kB), 256, attn_smem>>>(kmask);

    outproj_kernel<<<dim3((kS * kB) / 128, kD / 64), 256>>>(Wo, bo, out);
}

// round 3
// speedup vs baseline: 1.0540x; 1.0540x over previous
#include <cuda_runtime.h>
#include <math.h>

#define kS  1024
#define kB  4
#define kD  1024
#define kH  16
#define kDH 64

// Scratch (static device globals; no dynamic allocation allowed)
__device__ float g_q[kB*kH*kS*kDH];   // [b][h][s][dh]
__device__ float g_k[kB*kH*kS*kDH];
__device__ float g_v[kB*kH*kS*kDH];
__device__ float g_o[kS*kB*kH*kDH];   // [s][b][h*DH+dh] (concat layout for final GEMM)

// ---- packed f32x2 helpers (Blackwell FFMA2) ----
typedef unsigned long long ull;
__device__ __forceinline__ ull pk2(float lo, float hi) {
    ull r; asm("mov.b64 %0, {%1, %2};" : "=l"(r) : "f"(lo), "f"(hi)); return r;
}
__device__ __forceinline__ ull dup2(float v) {
    ull r; asm("mov.b64 %0, {%1, %1};" : "=l"(r) : "f"(v)); return r;
}
__device__ __forceinline__ ull fma2(ull a, ull b, ull c) {
    ull d; asm("fma.rn.f32x2 %0, %1, %2, %3;" : "=l"(d) : "l"(a), "l"(b), "l"(c)); return d;
}
__device__ __forceinline__ void upk2(ull v, float& lo, float& hi) {
    asm("mov.b64 {%0, %1}, %2;" : "=f"(lo), "=f"(hi) : "l"(v));
}

// ---------------------------------------------------------------------------
// Kernel 1: per-head projection  out[b,h,s,:] = act[s,b,:] @ W[h,:,:] + bias
// BM=128, BN=64 (=DH), BK=16. 128 threads, 8x8 register tile, FFMA2 packed
// along M (M-pairs free from LDS.128; B duplicated via mov.b64 on ALU pipe).
// ---------------------------------------------------------------------------
__global__ void __launch_bounds__(128) proj_kernel(
    const float* __restrict__ act,   // [S, B, D]
    const float* __restrict__ W,     // [H, D, DH]
    const float* __restrict__ bias,  // [H, DH]
    int which)
{
    float* out = (which == 0) ? g_q : (which == 1) ? g_k : g_v;
    int s0 = blockIdx.x * 128;
    int h  = blockIdx.y;
    int b  = blockIdx.z;

    __shared__ float As[16][128];
    __shared__ float Bs[16][64];

    int tid = threadIdx.x;
    int ty = tid >> 3;          // 0..15 : M group of 8
    int tx = tid & 7;           // 0..7  : N group of 8

    ull acc[4][8];
    #pragma unroll
    for (int i = 0; i < 4; i++)
        #pragma unroll
        for (int j = 0; j < 8; j++) acc[i][j] = 0ull;

    for (int k0 = 0; k0 < kD; k0 += 16) {
        // load A tile: 512 float4s, scatter to [kk][m]
        #pragma unroll
        for (int i = 0; i < 4; i++) {
            int id = tid + i * 128;
            int m  = id >> 2;
            int k4 = (id & 3) * 4;
            float4 va = *(const float4*)(act + ((size_t)(s0 + m) * kB + b) * kD + k0 + k4);
            As[k4 + 0][m] = va.x; As[k4 + 1][m] = va.y;
            As[k4 + 2][m] = va.z; As[k4 + 3][m] = va.w;
        }
        // load B tile: 256 float4s
        #pragma unroll
        for (int i = 0; i < 2; i++) {
            int id = tid + i * 128;
            int kk = id >> 4;
            int n4 = (id & 15) * 4;
            *(float4*)&Bs[kk][n4] = *(const float4*)(W + ((size_t)h * kD + k0 + kk) * kDH + n4);
        }
        __syncthreads();

        #pragma unroll
        for (int kk = 0; kk < 16; kk++) {
            float4 a0 = *(const float4*)&As[kk][ty * 8];
            float4 a1 = *(const float4*)&As[kk][ty * 8 + 4];
            ull pa[4] = { pk2(a0.x, a0.y), pk2(a0.z, a0.w),
                          pk2(a1.x, a1.y), pk2(a1.z, a1.w) };
            float4 b0 = *(const float4*)&Bs[kk][tx * 8];
            float4 b1 = *(const float4*)&Bs[kk][tx * 8 + 4];
            ull pb[8] = { dup2(b0.x), dup2(b0.y), dup2(b0.z), dup2(b0.w),
                          dup2(b1.x), dup2(b1.y), dup2(b1.z), dup2(b1.w) };
            #pragma unroll
            for (int i = 0; i < 4; i++)
                #pragma unroll
                for (int j = 0; j < 8; j++)
                    acc[i][j] = fma2(pa[i], pb[j], acc[i][j]);
        }
        __syncthreads();
    }

    float4 bv0 = *(const float4*)(bias + h * kDH + tx * 8);
    float4 bv1 = *(const float4*)(bias + h * kDH + tx * 8 + 4);
    float bb[8] = {bv0.x, bv0.y, bv0.z, bv0.w, bv1.x, bv1.y, bv1.z, bv1.w};

    #pragma unroll
    for (int i = 0; i < 4; i++) {
        float lo[8], hi[8];
        #pragma unroll
        for (int j = 0; j < 8; j++) upk2(acc[i][j], lo[j], hi[j]);
        size_t r_lo = (((size_t)b * kH + h) * kS + s0 + ty * 8 + 2 * i) * kDH + tx * 8;
        size_t r_hi = r_lo + kDH;
        float4 o;
        o.x = lo[0]+bb[0]; o.y = lo[1]+bb[1]; o.z = lo[2]+bb[2]; o.w = lo[3]+bb[3];
        *(float4*)(out + r_lo) = o;
        o.x = lo[4]+bb[4]; o.y = lo[5]+bb[5]; o.z = lo[6]+bb[6]; o.w = lo[7]+bb[7];
        *(float4*)(out + r_lo + 4) = o;
        o.x = hi[0]+bb[0]; o.y = hi[1]+bb[1]; o.z = hi[2]+bb[2]; o.w = hi[3]+bb[3];
        *(float4*)(out + r_hi) = o;
        o.x = hi[4]+bb[4]; o.y = hi[5]+bb[5]; o.z = hi[6]+bb[6]; o.w = hi[7]+bb[7];
        *(float4*)(out + r_hi + 4) = o;
    }
}

// ---------------------------------------------------------------------------
// Kernel 2: attention per (b,h). Non-online softmax (scores bounded; masked
// entries exp to exactly 0). FFMA2-packed score & output accumulation.
// ---------------------------------------------------------------------------
__global__ void __launch_bounds__(256) attn_kernel(const int* __restrict__ mask)
{
    extern __shared__ float smf[];
    float* Qs = smf;                  // [64][64]
    float* Ks = Qs + 64 * 64;         // [64][68]
    float* Ps = Ks + 64 * 68;         // [64][68]
    float* Vs = Ps + 64 * 68;         // [64][64]
    float* Mk = Vs + 64 * 64;         // [64]

    int s0 = blockIdx.x * 64;
    int h  = blockIdx.y;
    int b  = blockIdx.z;
    int tid  = threadIdx.x;
    int warp = tid >> 5, lane = tid & 31;

    const size_t base = ((size_t)b * kH + h) * kS * kDH;
    const float* qb = g_q + base;
    const float* kb = g_k + base;
    const float* vb = g_v + base;

    #pragma unroll
    for (int i = 0; i < 4; i++) {
        int idx = tid + i * 256;
        int r = idx >> 4, k4 = (idx & 15) * 4;
        *(float4*)&Qs[r * 64 + k4] = *(const float4*)(qb + (size_t)(s0 + r) * kDH + k4);
    }

    int r0 = warp * 8;
    int d0 = lane, d1 = lane + 32;
    ull   po[8];
    float l_run[8];
    #pragma unroll
    for (int r = 0; r < 8; r++) { po[r] = 0ull; l_run[r] = 0.f; }

    const float scale = 0.125f;  // 1/sqrt(64)

    for (int j0 = 0; j0 < kS; j0 += 64) {
        __syncthreads();
        #pragma unroll
        for (int i = 0; i < 4; i++) {
            int idx = tid + i * 256;
            int c = idx >> 4, k4 = (idx & 15) * 4;
            *(float4*)&Ks[c * 68 + k4] = *(const float4*)(kb + (size_t)(j0 + c) * kDH + k4);
            *(float4*)&Vs[c * 64 + k4] = *(const float4*)(vb + (size_t)(j0 + c) * kDH + k4);
        }
        if (tid < 64) Mk[tid] = (float)mask[(size_t)(j0 + tid) * kB + b] * 1e18f;
        __syncthreads();

        // ---- scores: S = Q @ K^T (pair = (col d0, col d1)) ----
        ull ps[8];
        #pragma unroll
        for (int r = 0; r < 8; r++) ps[r] = 0ull;
        #pragma unroll
        for (int k4 = 0; k4 < 64; k4 += 4) {
            float4 kc0 = *(const float4*)&Ks[d0 * 68 + k4];
            float4 kc1 = *(const float4*)&Ks[d1 * 68 + k4];
            ull pk0 = pk2(kc0.x, kc1.x), pk1 = pk2(kc0.y, kc1.y);
            ull pk2_ = pk2(kc0.z, kc1.z), pk3 = pk2(kc0.w, kc1.w);
            #pragma unroll
            for (int r = 0; r < 8; r++) {
                float4 q = *(const float4*)&Qs[(r0 + r) * 64 + k4];
                ps[r] = fma2(dup2(q.x), pk0,  ps[r]);
                ps[r] = fma2(dup2(q.y), pk1,  ps[r]);
                ps[r] = fma2(dup2(q.z), pk2_, ps[r]);
                ps[r] = fma2(dup2(q.w), pk3,  ps[r]);
            }
        }

        // ---- softmax weights (no running max; masked -> exp(-1e18)=0) ----
        float mk0 = Mk[d0], mk1 = Mk[d1];
        #pragma unroll
        for (int r = 0; r < 8; r++) {
            float a0, a1;
            upk2(ps[r], a0, a1);
            float p0 = __expf(fminf(a0 * scale - mk0, 60.f));
            float p1 = __expf(fminf(a1 * scale - mk1, 60.f));
            l_run[r] += p0 + p1;
            Ps[(r0 + r) * 68 + d0] = p0;
            Ps[(r0 + r) * 68 + d1] = p1;
        }
        __syncwarp();

        // ---- O += P @ V (pair = (col d0, col d1)) ----
        #pragma unroll
        for (int c4 = 0; c4 < 64; c4 += 4) {
            ull pv0 = pk2(Vs[(c4 + 0) * 64 + d0], Vs[(c4 + 0) * 64 + d1]);
            ull pv1 = pk2(Vs[(c4 + 1) * 64 + d0], Vs[(c4 + 1) * 64 + d1]);
            ull pv2 = pk2(Vs[(c4 + 2) * 64 + d0], Vs[(c4 + 2) * 64 + d1]);
            ull pv3 = pk2(Vs[(c4 + 3) * 64 + d0], Vs[(c4 + 3) * 64 + d1]);
            #pragma unroll
            for (int r = 0; r < 8; r++) {
                float4 p = *(const float4*)&Ps[(r0 + r) * 68 + c4];
                po[r] = fma2(dup2(p.x), pv0, po[r]);
                po[r] = fma2(dup2(p.y), pv1, po[r]);
                po[r] = fma2(dup2(p.z), pv2, po[r]);
                po[r] = fma2(dup2(p.w), pv3, po[r]);
            }
        }
    }

    #pragma unroll
    for (int r = 0; r < 8; r++) {
        float l = l_run[r];
        #pragma unroll
        for (int off = 16; off > 0; off >>= 1)
            l += __shfl_xor_sync(0xffffffffu, l, off);
        float inv = 1.0f / l;
        float o0, o1;
        upk2(po[r], o0, o1);
        size_t row = ((size_t)(s0 + r0 + r) * kB + b) * (kH * kDH) + (size_t)h * kDH;
        g_o[row + d0] = o0 * inv;
        g_o[row + d1] = o1 * inv;
    }
}

// ---------------------------------------------------------------------------
// Kernel 3: output projection  out[4096,1024] = g_o @ Wo + bo
// Same FFMA2 8x8 tiling, BM=128/BN=64/BK=16, 128 threads.
// ---------------------------------------------------------------------------
__global__ void __launch_bounds__(128) outproj_kernel(
    const float* __restrict__ Wo,   // [1024, 1024]
    const float* __restrict__ bo,   // [1024]
    float* __restrict__ out)        // [S*B, 1024]
{
    int m0 = blockIdx.x * 128;
    int n0 = blockIdx.y * 64;

    __shared__ float As[16][128];
    __shared__ float Bs[16][64];

    int tid = threadIdx.x;
    int ty = tid >> 3;
    int tx = tid & 7;

    ull acc[4][8];
    #pragma unroll
    for (int i = 0; i < 4; i++)
        #pragma unroll
        for (int j = 0; j < 8; j++) acc[i][j] = 0ull;

    for (int k0 = 0; k0 < kH * kDH; k0 += 16) {
        #pragma unroll
        for (int i = 0; i < 4; i++) {
            int id = tid + i * 128;
            int m  = id >> 2;
            int k4 = (id & 3) * 4;
            float4 va = *(const float4*)(g_o + (size_t)(m0 + m) * (kH * kDH) + k0 + k4);
            As[k4 + 0][m] = va.x; As[k4 + 1][m] = va.y;
            As[k4 + 2][m] = va.z; As[k4 + 3][m] = va.w;
        }
        #pragma unroll
        for (int i = 0; i < 2; i++) {
            int id = tid + i * 128;
            int kk = id >> 4;
            int n4 = (id & 15) * 4;
            *(float4*)&Bs[kk][n4] = *(const float4*)(Wo + (size_t)(k0 + kk) * kD + n0 + n4);
        }
        __syncthreads();

        #pragma unroll
        for (int kk = 0; kk < 16; kk++) {
            float4 a0 = *(const float4*)&As[kk][ty * 8];
            float4 a1 = *(const float4*)&As[kk][ty * 8 + 4];
            ull pa[4] = { pk2(a0.x, a0.y), pk2(a0.z, a0.w),
                          pk2(a1.x, a1.y), pk2(a1.z, a1.w) };
            float4 b0 = *(const float4*)&Bs[kk][tx * 8];
            float4 b1 = *(const float4*)&Bs[kk][tx * 8 + 4];
            ull pb[8] = { dup2(b0.x), dup2(b0.y), dup2(b0.z), dup2(b0.w),
                          dup2(b1.x), dup2(b1.y), dup2(b1.z), dup2(b1.w) };
            #pragma unroll
            for (int i = 0; i < 4; i++)
                #pragma unroll
                for (int j = 0; j < 8; j++)
                    acc[i][j] = fma2(pa[i], pb[j], acc[i][j]);
        }
        __syncthreads();
    }

    float4 bv0 = *(const float4*)(bo + n0 + tx * 8);
    float4 bv1 = *(const float4*)(bo + n0 + tx * 8 + 4);
    float bb[8] = {bv0.x, bv0.y, bv0.z, bv0.w, bv1.x, bv1.y, bv1.z, bv1.w};

    #pragma unroll
    for (int i = 0; i < 4; i++) {
        float lo[8], hi[8];
        #pragma unroll
        for (int j = 0; j < 8; j++) upk2(acc[i][j], lo[j], hi[j]);
        size_t r_lo = (size_t)(m0 + ty * 8 + 2 * i) * kD + n0 + tx * 8;
        size_t r_hi = r_lo + kD;
        float4 o;
        o.x = lo[0]+bb[0]; o.y = lo[1]+bb[1]; o.z = lo[2]+bb[2]; o.w = lo[3]+bb[3];
        *(float4*)(out + r_lo) = o;
        o.x = lo[4]+bb[4]; o.y = lo[5]+bb[5]; o.z = lo[6]+bb[6]; o.w = lo[7]+bb[7];
        *(float4*)(out + r_lo + 4) = o;
        o.x = hi[0]+bb[0]; o.y = hi[1]+bb[1]; o.z = hi[2]+bb[2]; o.w = hi[3]+bb[3];
        *(float4*)(out + r_hi) = o;
        o.x = hi[4]+bb[4]; o.y = hi[5]+bb[5]; o.z = hi[6]+bb[6]; o.w = hi[7]+bb[7];
        *(float4*)(out + r_hi + 4) = o;
    }
}

// ---------------------------------------------------------------------------
extern "C" void kernel_launch(void* const* d_in, const int* in_sizes, int n_in,
                              void* d_out, int out_size) {
    (void)in_sizes; (void)n_in; (void)out_size;
    const float* query = (const float*)d_in[0];
    const float* key   = (const float*)d_in[1];
    const float* value = (const float*)d_in[2];
    const int*   kmask = (const int*)  d_in[3];
    const float* Wq    = (const float*)d_in[4];
    const float* bq    = (const float*)d_in[5];
    const float* Wk    = (const float*)d_in[6];
    const float* bk    = (const float*)d_in[7];
    const float* Wv    = (const float*)d_in[8];
    const float* bvp   = (const float*)d_in[9];
    const float* Wo    = (const float*)d_in[10];
    const float* bo    = (const float*)d_in[11];
    float* out = (float*)d_out;

    dim3 pg(kS / 128, kH, kB);
    proj_kernel<<<pg, 128>>>(query, Wq, bq, 0);
    proj_kernel<<<pg, 128>>>(key,   Wk, bk, 1);
    proj_kernel<<<pg, 128>>>(value, Wv, bvp, 2);

    int attn_smem = (64 * 64 + 64 * 68 + 64 * 68 + 64 * 64 + 64) * (int)sizeof(float);
    cudaFuncSetAttribute(attn_kernel, cudaFuncAttributeMaxDynamicSharedMemorySize, attn_smem);
    attn_kernel<<<dim3(kS / 64, kH, kB), 256, attn_smem>>>(kmask);

    outproj_kernel<<<dim3((kS * kB) / 128, kD / 64), 128>>>(Wo, bo, out);
}

// round 5
// speedup vs baseline: 1.6276x; 1.5443x over previous
#include <cuda_runtime.h>
#include <cuda_bf16.h>
#include <math.h>
#include <cstdint>

#define kS  1024
#define kB  4
#define kD  1024
#define kH  16
#define kDH 64

// fp32 scratch
__device__ float g_q[kB*kH*kS*kDH];   // [b][h][s][dh]
__device__ float g_k[kB*kH*kS*kDH];
__device__ float g_v[kB*kH*kS*kDH];
__device__ float g_o[kS*kB*kH*kDH];   // [s][b][h*DH+dh]

// bf16 split scratch (hi + residual-lo)
__device__ __nv_bfloat16 g_qa_hi[kS*kB*kD], g_qa_lo[kS*kB*kD];
__device__ __nv_bfloat16 g_ka_hi[kS*kB*kD], g_ka_lo[kS*kB*kD];
__device__ __nv_bfloat16 g_va_hi[kS*kB*kD], g_va_lo[kS*kB*kD];
__device__ __nv_bfloat16 g_oa_hi[kS*kB*kD], g_oa_lo[kS*kB*kD];
__device__ __nv_bfloat16 g_wq_hi[kH*kDH*kD], g_wq_lo[kH*kDH*kD];   // [h][n][k]
__device__ __nv_bfloat16 g_wk_hi[kH*kDH*kD], g_wk_lo[kH*kDH*kD];
__device__ __nv_bfloat16 g_wv_hi[kH*kDH*kD], g_wv_lo[kH*kDH*kD];
__device__ __nv_bfloat16 g_wo_hi[kD*kD],     g_wo_lo[kD*kD];       // [n][k]

// ===================== helpers =====================
__device__ __forceinline__ uint32_t smem_u32(const void* p) {
    uint32_t a;
    asm("{ .reg .u64 t; cvta.to.shared.u64 t, %1; cvt.u32.u64 %0, t; }" : "=r"(a) : "l"(p));
    return a;
}
__device__ __forceinline__ void ldmatrix_x4(uint32_t* r, uint32_t a) {
    asm volatile("ldmatrix.sync.aligned.m8n8.x4.shared.b16 {%0,%1,%2,%3}, [%4];"
        : "=r"(r[0]), "=r"(r[1]), "=r"(r[2]), "=r"(r[3]) : "r"(a));
}
__device__ __forceinline__ void mma_bf16(float* c, const uint32_t* a, const uint32_t* b) {
    asm volatile("mma.sync.aligned.m16n8k16.row.col.f32.bf16.bf16.f32 "
        "{%0,%1,%2,%3},{%4,%5,%6,%7},{%8,%9},{%0,%1,%2,%3};"
        : "+f"(c[0]), "+f"(c[1]), "+f"(c[2]), "+f"(c[3])
        : "r"(a[0]), "r"(a[1]), "r"(a[2]), "r"(a[3]), "r"(b[0]), "r"(b[1]));
}

// ===========================================================================
// Prep 1: elementwise fp32 -> (bf16 hi, bf16 residual lo)
// ===========================================================================
__global__ void __launch_bounds__(256) split_kernel(
    const float* __restrict__ src,
    __nv_bfloat16* __restrict__ hi, __nv_bfloat16* __restrict__ lo, int n4)
{
    int i = blockIdx.x * blockDim.x + threadIdx.x;
    if (i >= n4) return;
    float4 v = ((const float4*)src)[i];
    float f[4] = {v.x, v.y, v.z, v.w};
    uint32_t hv[2], lv[2];
    #pragma unroll
    for (int p = 0; p < 2; p++) {
        __nv_bfloat16 h0 = __float2bfloat16_rn(f[2*p+0]);
        __nv_bfloat16 h1 = __float2bfloat16_rn(f[2*p+1]);
        __nv_bfloat16 l0 = __float2bfloat16_rn(f[2*p+0] - __bfloat162float(h0));
        __nv_bfloat16 l1 = __float2bfloat16_rn(f[2*p+1] - __bfloat162float(h1));
        hv[p] = (uint32_t)__bfloat16_as_ushort(h0) | ((uint32_t)__bfloat16_as_ushort(h1) << 16);
        lv[p] = (uint32_t)__bfloat16_as_ushort(l0) | ((uint32_t)__bfloat16_as_ushort(l1) << 16);
    }
    *(uint2*)(hi + (size_t)i * 4) = make_uint2(hv[0], hv[1]);
    *(uint2*)(lo + (size_t)i * 4) = make_uint2(lv[0], lv[1]);
}

// ===========================================================================
// Prep 2: transpose + split.  src[z][R][C] fp32 -> dst[z][C][R] bf16 hi/lo
// block (32,8), grid (C/32, R/32, Z)
// ===========================================================================
__global__ void __launch_bounds__(256) transpose_split_kernel(
    const float* __restrict__ src,
    __nv_bfloat16* __restrict__ hi, __nv_bfloat16* __restrict__ lo, int R, int C)
{
    __shared__ float tile[32][33];
    int z = blockIdx.z;
    int c0 = blockIdx.x * 32, r0 = blockIdx.y * 32;
    int tx = threadIdx.x, ty = threadIdx.y;
    const float* s = src + (size_t)z * R * C;
    #pragma unroll
    for (int i = 0; i < 4; i++)
        tile[ty + i * 8][tx] = s[(size_t)(r0 + ty + i * 8) * C + c0 + tx];
    __syncthreads();
    __nv_bfloat16* ph = hi + (size_t)z * R * C;
    __nv_bfloat16* pl = lo + (size_t)z * R * C;
    #pragma unroll
    for (int i = 0; i < 4; i++) {
        float v = tile[tx][ty + i * 8];          // src[r0+tx][c0+ty+i*8]
        __nv_bfloat16 h = __float2bfloat16_rn(v);
        __nv_bfloat16 l = __float2bfloat16_rn(v - __bfloat162float(h));
        size_t o = (size_t)(c0 + ty + i * 8) * R + r0 + tx;
        ph[o] = h;
        pl[o] = l;
    }
}

// ===========================================================================
// mma.sync GEMM tiles: BM=128, BN=64, BK=64, 256 thr (8 warps, 4x2 warp grid,
// 32x32 per warp). 3-pass bf16 split. smem rows padded to 72 bf16 (144B).
// ===========================================================================
#define GA0 0
#define GA1 (128*144)
#define GB0 (2*128*144)
#define GB1 (2*128*144 + 64*144)
#define GEMM_SMEM (2*128*144 + 2*64*144)   // 55296 B

struct Frag { uint32_t r[4]; };

__device__ __forceinline__ void gemm_mainloop_step(
    uint32_t sbase, int wm, int wn, int lane, float acc[2][4][4])
{
    #pragma unroll
    for (int ks = 0; ks < 4; ks++) {
        int kofs = ks * 16;
        uint32_t a0f[2][4], a1f[2][4], b0f[4][2], b1f[4][2];
        #pragma unroll
        for (int mt = 0; mt < 2; mt++) {
            uint32_t addr = sbase + GA0
                + (uint32_t)(wm * 32 + mt * 16 + (lane & 15)) * 144
                + (uint32_t)(kofs + (lane >> 4) * 8) * 2;
            ldmatrix_x4(a0f[mt], addr);
            ldmatrix_x4(a1f[mt], addr + (GA1 - GA0));
        }
        #pragma unroll
        for (int nt2 = 0; nt2 < 2; nt2++) {
            uint32_t addr = sbase + GB0
                + (uint32_t)(wn * 32 + nt2 * 16 + (lane & 15)) * 144
                + (uint32_t)(kofs + (lane >> 4) * 8) * 2;
            uint32_t t[4];
            ldmatrix_x4(t, addr);
            b0f[nt2 * 2 + 0][0] = t[0]; b0f[nt2 * 2 + 0][1] = t[2];
            b0f[nt2 * 2 + 1][0] = t[1]; b0f[nt2 * 2 + 1][1] = t[3];
            ldmatrix_x4(t, addr + (GB1 - GB0));
            b1f[nt2 * 2 + 0][0] = t[0]; b1f[nt2 * 2 + 0][1] = t[2];
            b1f[nt2 * 2 + 1][0] = t[1]; b1f[nt2 * 2 + 1][1] = t[3];
        }
        #pragma unroll
        for (int mt = 0; mt < 2; mt++)
            #pragma unroll
            for (int nt = 0; nt < 4; nt++) {
                mma_bf16(acc[mt][nt], a0f[mt], b0f[nt]);
                mma_bf16(acc[mt][nt], a0f[mt], b1f[nt]);
                mma_bf16(acc[mt][nt], a1f[mt], b0f[nt]);
            }
    }
}

// ---- projection: out[b,h,s,dh] = act[s,b,:] @ Wt[h,dh,:] + bias ----
__global__ void __launch_bounds__(256) proj_mma_kernel(
    const __nv_bfloat16* __restrict__ a_hi, const __nv_bfloat16* __restrict__ a_lo,
    const __nv_bfloat16* __restrict__ w_hi, const __nv_bfloat16* __restrict__ w_lo,
    const float* __restrict__ bias, int which)
{
    float* out = (which == 0) ? g_q : (which == 1) ? g_k : g_v;
    extern __shared__ char smem[];
    uint32_t sbase = smem_u32(smem);
    int s0 = blockIdx.x * 128;
    int h  = blockIdx.y;
    int b  = blockIdx.z;
    int tid = threadIdx.x;
    int wid = tid >> 5, lane = tid & 31;
    int wm = wid >> 1, wn = wid & 1;

    float acc[2][4][4];
    #pragma unroll
    for (int mt = 0; mt < 2; mt++)
        #pragma unroll
        for (int nt = 0; nt < 4; nt++)
            #pragma unroll
            for (int e = 0; e < 4; e++) acc[mt][nt][e] = 0.f;

    for (int c = 0; c < 16; c++) {
        __syncthreads();
        int k0 = c * 64;
        #pragma unroll
        for (int i = 0; i < 4; i++) {
            int id = tid + i * 256;
            int m = id >> 3, k8 = id & 7;
            size_t g = ((size_t)(s0 + m) * kB + b) * kD + k0 + k8 * 8;
            *(uint4*)(smem + GA0 + m * 144 + k8 * 16) = *(const uint4*)(a_hi + g);
            *(uint4*)(smem + GA1 + m * 144 + k8 * 16) = *(const uint4*)(a_lo + g);
        }
        #pragma unroll
        for (int i = 0; i < 2; i++) {
            int id = tid + i * 256;
            int n = id >> 3, k8 = id & 7;
            size_t g = ((size_t)h * kDH + n) * kD + k0 + k8 * 8;
            *(uint4*)(smem + GB0 + n * 144 + k8 * 16) = *(const uint4*)(w_hi + g);
            *(uint4*)(smem + GB1 + n * 144 + k8 * 16) = *(const uint4*)(w_lo + g);
        }
        __syncthreads();
        gemm_mainloop_step(sbase, wm, wn, lane, acc);
    }

    int gq = lane >> 2, tg = lane & 3;
    #pragma unroll
    for (int mt = 0; mt < 2; mt++) {
        int row = s0 + wm * 32 + mt * 16 + gq;
        #pragma unroll
        for (int nt = 0; nt < 4; nt++) {
            int col = wn * 32 + nt * 8 + tg * 2;
            float b0 = bias[h * kDH + col], b1 = bias[h * kDH + col + 1];
            size_t r0 = (((size_t)b * kH + h) * kS + row) * kDH + col;
            *(float2*)(out + r0) = make_float2(acc[mt][nt][0] + b0, acc[mt][nt][1] + b1);
            *(float2*)(out + r0 + 8 * kDH) = make_float2(acc[mt][nt][2] + b0, acc[mt][nt][3] + b1);
        }
    }
}

// ---- output projection: out[4096,1024] = g_o @ Wo + bo ----
__global__ void __launch_bounds__(256) outproj_mma_kernel(
    const float* __restrict__ bo, float* __restrict__ out)
{
    extern __shared__ char smem[];
    uint32_t sbase = smem_u32(smem);
    int m0 = blockIdx.x * 128;
    int n0 = blockIdx.y * 64;
    int tid = threadIdx.x;
    int wid = tid >> 5, lane = tid & 31;
    int wm = wid >> 1, wn = wid & 1;

    float acc[2][4][4];
    #pragma unroll
    for (int mt = 0; mt < 2; mt++)
        #pragma unroll
        for (int nt = 0; nt < 4; nt++)
            #pragma unroll
            for (int e = 0; e < 4; e++) acc[mt][nt][e] = 0.f;

    for (int c = 0; c < 16; c++) {
        __syncthreads();
        int k0 = c * 64;
        #pragma unroll
        for (int i = 0; i < 4; i++) {
            int id = tid + i * 256;
            int m = id >> 3, k8 = id & 7;
            size_t g = (size_t)(m0 + m) * kD + k0 + k8 * 8;
            *(uint4*)(smem + GA0 + m * 144 + k8 * 16) = *(const uint4*)(g_oa_hi + g);
            *(uint4*)(smem + GA1 + m * 144 + k8 * 16) = *(const uint4*)(g_oa_lo + g);
        }
        #pragma unroll
        for (int i = 0; i < 2; i++) {
            int id = tid + i * 256;
            int n = id >> 3, k8 = id & 7;
            size_t g = (size_t)(n0 + n) * kD + k0 + k8 * 8;
            *(uint4*)(smem + GB0 + n * 144 + k8 * 16) = *(const uint4*)(g_wo_hi + g);
            *(uint4*)(smem + GB1 + n * 144 + k8 * 16) = *(const uint4*)(g_wo_lo + g);
        }
        __syncthreads();
        gemm_mainloop_step(sbase, wm, wn, lane, acc);
    }

    int gq = lane >> 2, tg = lane & 3;
    #pragma unroll
    for (int mt = 0; mt < 2; mt++) {
        int row = m0 + wm * 32 + mt * 16 + gq;
        #pragma unroll
        for (int nt = 0; nt < 4; nt++) {
            int col = n0 + wn * 32 + nt * 8 + tg * 2;
            float b0 = bo[col], b1 = bo[col + 1];
            size_t r0 = (size_t)row * kD + col;
            *(float2*)(out + r0) = make_float2(acc[mt][nt][0] + b0, acc[mt][nt][1] + b1);
            *(float2*)(out + r0 + 8 * kD) = make_float2(acc[mt][nt][2] + b0, acc[mt][nt][3] + b1);
        }
    }
}

// ===========================================================================
// Attention (round-3 version, FFMA2, non-online softmax)
// ===========================================================================
typedef unsigned long long ull;
__device__ __forceinline__ ull pk2(float lo, float hi) {
    ull r; asm("mov.b64 %0, {%1, %2};" : "=l"(r) : "f"(lo), "f"(hi)); return r;
}
__device__ __forceinline__ ull dup2(float v) {
    ull r; asm("mov.b64 %0, {%1, %1};" : "=l"(r) : "f"(v)); return r;
}
__device__ __forceinline__ ull fma2(ull a, ull b, ull c) {
    ull d; asm("fma.rn.f32x2 %0, %1, %2, %3;" : "=l"(d) : "l"(a), "l"(b), "l"(c)); return d;
}
__device__ __forceinline__ void upk2(ull v, float& lo, float& hi) {
    asm("mov.b64 {%0, %1}, %2;" : "=f"(lo), "=f"(hi) : "l"(v));
}

__global__ void __launch_bounds__(256) attn_kernel(const int* __restrict__ mask)
{
    extern __shared__ float smf[];
    float* Qs = smf;                  // [64][64]
    float* Ks = Qs + 64 * 64;         // [64][68]
    float* Ps = Ks + 64 * 68;         // [64][68]
    float* Vs = Ps + 64 * 68;         // [64][64]
    float* Mk = Vs + 64 * 64;         // [64]

    int s0 = blockIdx.x * 64;
    int h  = blockIdx.y;
    int b  = blockIdx.z;
    int tid  = threadIdx.x;
    int warp = tid >> 5, lane = tid & 31;

    const size_t base = ((size_t)b * kH + h) * kS * kDH;
    const float* qb = g_q + base;
    const float* kb = g_k + base;
    const float* vb = g_v + base;

    #pragma unroll
    for (int i = 0; i < 4; i++) {
        int idx = tid + i * 256;
        int r = idx >> 4, k4 = (idx & 15) * 4;
        *(float4*)&Qs[r * 64 + k4] = *(const float4*)(qb + (size_t)(s0 + r) * kDH + k4);
    }

    int r0 = warp * 8;
    int d0 = lane, d1 = lane + 32;
    ull   po[8];
    float l_run[8];
    #pragma unroll
    for (int r = 0; r < 8; r++) { po[r] = 0ull; l_run[r] = 0.f; }

    const float scale = 0.125f;

    for (int j0 = 0; j0 < kS; j0 += 64) {
        __syncthreads();
        #pragma unroll
        for (int i = 0; i < 4; i++) {
            int idx = tid + i * 256;
            int c = idx >> 4, k4 = (idx & 15) * 4;
            *(float4*)&Ks[c * 68 + k4] = *(const float4*)(kb + (size_t)(j0 + c) * kDH + k4);
            *(float4*)&Vs[c * 64 + k4] = *(const float4*)(vb + (size_t)(j0 + c) * kDH + k4);
        }
        if (tid < 64) Mk[tid] = (float)mask[(size_t)(j0 + tid) * kB + b] * 1e18f;
        __syncthreads();

        ull ps[8];
        #pragma unroll
        for (int r = 0; r < 8; r++) ps[r] = 0ull;
        #pragma unroll
        for (int k4 = 0; k4 < 64; k4 += 4) {
            float4 kc0 = *(const float4*)&Ks[d0 * 68 + k4];
            float4 kc1 = *(const float4*)&Ks[d1 * 68 + k4];
            ull pka = pk2(kc0.x, kc1.x), pkb = pk2(kc0.y, kc1.y);
            ull pkc = pk2(kc0.z, kc1.z), pkd = pk2(kc0.w, kc1.w);
            #pragma unroll
            for (int r = 0; r < 8; r++) {
                float4 q = *(const float4*)&Qs[(r0 + r) * 64 + k4];
                ps[r] = fma2(dup2(q.x), pka, ps[r]);
                ps[r] = fma2(dup2(q.y), pkb, ps[r]);
                ps[r] = fma2(dup2(q.z), pkc, ps[r]);
                ps[r] = fma2(dup2(q.w), pkd, ps[r]);
            }
        }

        float mk0 = Mk[d0], mk1 = Mk[d1];
        #pragma unroll
        for (int r = 0; r < 8; r++) {
            float a0, a1;
            upk2(ps[r], a0, a1);
            float p0 = __expf(fminf(a0 * scale - mk0, 60.f));
            float p1 = __expf(fminf(a1 * scale - mk1, 60.f));
            l_run[r] += p0 + p1;
            Ps[(r0 + r) * 68 + d0] = p0;
            Ps[(r0 + r) * 68 + d1] = p1;
        }
        __syncwarp();

        #pragma unroll
        for (int c4 = 0; c4 < 64; c4 += 4) {
            ull pv0 = pk2(Vs[(c4 + 0) * 64 + d0], Vs[(c4 + 0) * 64 + d1]);
            ull pv1 = pk2(Vs[(c4 + 1) * 64 + d0], Vs[(c4 + 1) * 64 + d1]);
            ull pv2 = pk2(Vs[(c4 + 2) * 64 + d0], Vs[(c4 + 2) * 64 + d1]);
            ull pv3 = pk2(Vs[(c4 + 3) * 64 + d0], Vs[(c4 + 3) * 64 + d1]);
            #pragma unroll
            for (int r = 0; r < 8; r++) {
                float4 p = *(const float4*)&Ps[(r0 + r) * 68 + c4];
                po[r] = fma2(dup2(p.x), pv0, po[r]);
                po[r] = fma2(dup2(p.y), pv1, po[r]);
                po[r] = fma2(dup2(p.z), pv2, po[r]);
                po[r] = fma2(dup2(p.w), pv3, po[r]);
            }
        }
    }

    #pragma unroll
    for (int r = 0; r < 8; r++) {
        float l = l_run[r];
        #pragma unroll
        for (int off = 16; off > 0; off >>= 1)
            l += __shfl_xor_sync(0xffffffffu, l, off);
        float inv = 1.0f / l;
        float o0, o1;
        upk2(po[r], o0, o1);
        size_t row = ((size_t)(s0 + r0 + r) * kB + b) * (kH * kDH) + (size_t)h * kDH;
        g_o[row + d0] = o0 * inv;
        g_o[row + d1] = o1 * inv;
    }
}

// ---------------------------------------------------------------------------
extern "C" void kernel_launch(void* const* d_in, const int* in_sizes, int n_in,
                              void* d_out, int out_size) {
    (void)in_sizes; (void)n_in; (void)out_size;
    const float* query = (const float*)d_in[0];
    const float* key   = (const float*)d_in[1];
    const float* value = (const float*)d_in[2];
    const int*   kmask = (const int*)  d_in[3];
    const float* Wq    = (const float*)d_in[4];
    const float* bq    = (const float*)d_in[5];
    const float* Wk    = (const float*)d_in[6];
    const float* bk    = (const float*)d_in[7];
    const float* Wv    = (const float*)d_in[8];
    const float* bvp   = (const float*)d_in[9];
    const float* Wo    = (const float*)d_in[10];
    const float* bo    = (const float*)d_in[11];
    float* out = (float*)d_out;

    cudaFuncSetAttribute(proj_mma_kernel, cudaFuncAttributeMaxDynamicSharedMemorySize, GEMM_SMEM);
    cudaFuncSetAttribute(outproj_mma_kernel, cudaFuncAttributeMaxDynamicSharedMemorySize, GEMM_SMEM);
    int attn_smem = (64 * 64 + 64 * 68 + 64 * 68 + 64 * 64 + 64) * (int)sizeof(float);
    cudaFuncSetAttribute(attn_kernel, cudaFuncAttributeMaxDynamicSharedMemorySize, attn_smem);

    // resolve device-symbol addresses (host pointers to __device__ globals)
    __nv_bfloat16 *qa_hi, *qa_lo, *ka_hi, *ka_lo, *va_hi, *va_lo, *oa_hi, *oa_lo;
    __nv_bfloat16 *wq_hi, *wq_lo, *wk_hi, *wk_lo, *wv_hi, *wv_lo, *wo_hi, *wo_lo;
    cudaGetSymbolAddress((void**)&qa_hi, g_qa_hi); cudaGetSymbolAddress((void**)&qa_lo, g_qa_lo);
    cudaGetSymbolAddress((void**)&ka_hi, g_ka_hi); cudaGetSymbolAddress((void**)&ka_lo, g_ka_lo);
    cudaGetSymbolAddress((void**)&va_hi, g_va_hi); cudaGetSymbolAddress((void**)&va_lo, g_va_lo);
    cudaGetSymbolAddress((void**)&oa_hi, g_oa_hi); cudaGetSymbolAddress((void**)&oa_lo, g_oa_lo);
    cudaGetSymbolAddress((void**)&wq_hi, g_wq_hi); cudaGetSymbolAddress((void**)&wq_lo, g_wq_lo);
    cudaGetSymbolAddress((void**)&wk_hi, g_wk_hi); cudaGetSymbolAddress((void**)&wk_lo, g_wk_lo);
    cudaGetSymbolAddress((void**)&wv_hi, g_wv_hi); cudaGetSymbolAddress((void**)&wv_lo, g_wv_lo);
    cudaGetSymbolAddress((void**)&wo_hi, g_wo_hi); cudaGetSymbolAddress((void**)&wo_lo, g_wo_lo);
    float* go_ptr; cudaGetSymbolAddress((void**)&go_ptr, g_o);

    const int n4_act = kS * kB * kD / 4;   // 1M float4s

    // split activations
    split_kernel<<<n4_act / 256, 256>>>(query, qa_hi, qa_lo, n4_act);
    split_kernel<<<n4_act / 256, 256>>>(key,   ka_hi, ka_lo, n4_act);
    split_kernel<<<n4_act / 256, 256>>>(value, va_hi, va_lo, n4_act);

    // transpose + split weights:  W[h][d][n] -> Wt[h][n][d]
    transpose_split_kernel<<<dim3(kDH / 32, kD / 32, kH), dim3(32, 8)>>>(Wq, wq_hi, wq_lo, kD, kDH);
    transpose_split_kernel<<<dim3(kDH / 32, kD / 32, kH), dim3(32, 8)>>>(Wk, wk_hi, wk_lo, kD, kDH);
    transpose_split_kernel<<<dim3(kDH / 32, kD / 32, kH), dim3(32, 8)>>>(Wv, wv_hi, wv_lo, kD, kDH);
    // Wo[k][n] -> Wot[n][k]
    transpose_split_kernel<<<dim3(kD / 32, kD / 32, 1), dim3(32, 8)>>>(Wo, wo_hi, wo_lo, kD, kD);

    // projections (tensor core)
    dim3 pg(kS / 128, kH, kB);
    proj_mma_kernel<<<pg, 256, GEMM_SMEM>>>(qa_hi, qa_lo, wq_hi, wq_lo, bq, 0);
    proj_mma_kernel<<<pg, 256, GEMM_SMEM>>>(ka_hi, ka_lo, wk_hi, wk_lo, bk, 1);
    proj_mma_kernel<<<pg, 256, GEMM_SMEM>>>(va_hi, va_lo, wv_hi, wv_lo, bvp, 2);

    // attention
    attn_kernel<<<dim3(kS / 64, kH, kB), 256, attn_smem>>>(kmask);

    // split attention output, then output projection (tensor core)
    split_kernel<<<n4_act / 256, 256>>>(go_ptr, oa_hi, oa_lo, n4_act);
    outproj_mma_kernel<<<dim3((kS * kB) / 128, kD / 64), 256, GEMM_SMEM>>>(bo, out);
}

// round 7
// speedup vs baseline: 2.2837x; 1.4031x over previous
#include <cuda_runtime.h>
#include <cuda_bf16.h>
#include <math.h>
#include <cstdint>

#define kS  1024
#define kB  4
#define kD  1024
#define kH  16
#define kDH 64

// bf16 split scratch (hi + residual-lo)
__device__ __nv_bfloat16 g_qa_hi[kS*kB*kD], g_qa_lo[kS*kB*kD];   // activations
__device__ __nv_bfloat16 g_ka_hi[kS*kB*kD], g_ka_lo[kS*kB*kD];
__device__ __nv_bfloat16 g_va_hi[kS*kB*kD], g_va_lo[kS*kB*kD];
__device__ __nv_bfloat16 g_oa_hi[kS*kB*kD], g_oa_lo[kS*kB*kD];   // attn out (concat)
__device__ __nv_bfloat16 g_wq_hi[kH*kDH*kD], g_wq_lo[kH*kDH*kD]; // [h][n][k]
__device__ __nv_bfloat16 g_wk_hi[kH*kDH*kD], g_wk_lo[kH*kDH*kD];
__device__ __nv_bfloat16 g_wv_hi[kH*kDH*kD], g_wv_lo[kH*kDH*kD];
__device__ __nv_bfloat16 g_wo_hi[kD*kD],     g_wo_lo[kD*kD];     // [n][k]
// projected q/k/v in bf16 split
__device__ __nv_bfloat16 g_qp_hi[kB*kH*kS*kDH], g_qp_lo[kB*kH*kS*kDH]; // [b][h][s][dh]
__device__ __nv_bfloat16 g_kp_hi[kB*kH*kS*kDH], g_kp_lo[kB*kH*kS*kDH]; // [b][h][s][dh]
__device__ __nv_bfloat16 g_vp_hi[kB*kH*kS*kDH], g_vp_lo[kB*kH*kS*kDH]; // [b][h][dh][s] (transposed)

// ===================== helpers =====================
__device__ __forceinline__ uint32_t smem_u32(const void* p) {
    uint32_t a;
    asm("{ .reg .u64 t; cvta.to.shared.u64 t, %1; cvt.u32.u64 %0, t; }" : "=r"(a) : "l"(p));
    return a;
}
__device__ __forceinline__ void ldmatrix_x4(uint32_t* r, uint32_t a) {
    asm volatile("ldmatrix.sync.aligned.m8n8.x4.shared.b16 {%0,%1,%2,%3}, [%4];"
        : "=r"(r[0]), "=r"(r[1]), "=r"(r[2]), "=r"(r[3]) : "r"(a));
}
__device__ __forceinline__ void mma_bf16(float* c, const uint32_t* a, const uint32_t* b) {
    asm volatile("mma.sync.aligned.m16n8k16.row.col.f32.bf16.bf16.f32 "
        "{%0,%1,%2,%3},{%4,%5,%6,%7},{%8,%9},{%0,%1,%2,%3};"
        : "+f"(c[0]), "+f"(c[1]), "+f"(c[2]), "+f"(c[3])
        : "r"(a[0]), "r"(a[1]), "r"(a[2]), "r"(a[3]), "r"(b[0]), "r"(b[1]));
}
// split 2 floats -> packed bf16x2 hi + packed bf16x2 residual-lo
__device__ __forceinline__ void split_pack(float x, float y, uint32_t& hp, uint32_t& lp) {
    __nv_bfloat16 hx = __float2bfloat16_rn(x);
    __nv_bfloat16 hy = __float2bfloat16_rn(y);
    __nv_bfloat16 lx = __float2bfloat16_rn(x - __bfloat162float(hx));
    __nv_bfloat16 ly = __float2bfloat16_rn(y - __bfloat162float(hy));
    hp = (uint32_t)__bfloat16_as_ushort(hx) | ((uint32_t)__bfloat16_as_ushort(hy) << 16);
    lp = (uint32_t)__bfloat16_as_ushort(lx) | ((uint32_t)__bfloat16_as_ushort(ly) << 16);
}

// ===========================================================================
// Prep 1: elementwise fp32 -> (bf16 hi, bf16 residual lo)
// ===========================================================================
__global__ void __launch_bounds__(256) split_kernel(
    const float* __restrict__ src,
    __nv_bfloat16* __restrict__ hi, __nv_bfloat16* __restrict__ lo, int n4)
{
    int i = blockIdx.x * blockDim.x + threadIdx.x;
    if (i >= n4) return;
    float4 v = ((const float4*)src)[i];
    uint32_t h0, l0, h1, l1;
    split_pack(v.x, v.y, h0, l0);
    split_pack(v.z, v.w, h1, l1);
    *(uint2*)(hi + (size_t)i * 4) = make_uint2(h0, h1);
    *(uint2*)(lo + (size_t)i * 4) = make_uint2(l0, l1);
}

// ===========================================================================
// Prep 2: transpose + split.  src[z][R][C] fp32 -> dst[z][C][R] bf16 hi/lo
// ===========================================================================
__global__ void __launch_bounds__(256) transpose_split_kernel(
    const float* __restrict__ src,
    __nv_bfloat16* __restrict__ hi, __nv_bfloat16* __restrict__ lo, int R, int C)
{
    __shared__ float tile[32][33];
    int z = blockIdx.z;
    int c0 = blockIdx.x * 32, r0 = blockIdx.y * 32;
    int tx = threadIdx.x, ty = threadIdx.y;
    const float* s = src + (size_t)z * R * C;
    #pragma unroll
    for (int i = 0; i < 4; i++)
        tile[ty + i * 8][tx] = s[(size_t)(r0 + ty + i * 8) * C + c0 + tx];
    __syncthreads();
    __nv_bfloat16* ph = hi + (size_t)z * R * C;
    __nv_bfloat16* pl = lo + (size_t)z * R * C;
    #pragma unroll
    for (int i = 0; i < 4; i++) {
        float v = tile[tx][ty + i * 8];
        __nv_bfloat16 h = __float2bfloat16_rn(v);
        __nv_bfloat16 l = __float2bfloat16_rn(v - __bfloat162float(h));
        size_t o = (size_t)(c0 + ty + i * 8) * R + r0 + tx;
        ph[o] = h;
        pl[o] = l;
    }
}

// ===========================================================================
// mma.sync GEMM: BM=128, BN=64, BK=64, 256 thr (8 warps, 4x2), 3-pass split.
// ===========================================================================
#define GA0 0
#define GA1 (128*144)
#define GB0 (2*128*144)
#define GB1 (2*128*144 + 64*144)
#define GEMM_SMEM (2*128*144 + 2*64*144)   // 55296 B

__device__ __forceinline__ void gemm_mainloop_step(
    uint32_t sbase, int wm, int wn, int lane, float acc[2][4][4])
{
    #pragma unroll
    for (int ks = 0; ks < 4; ks++) {
        int kofs = ks * 16;
        uint32_t a0f[2][4], a1f[2][4], b0f[4][2], b1f[4][2];
        #pragma unroll
        for (int mt = 0; mt < 2; mt++) {
            uint32_t addr = sbase + GA0
                + (uint32_t)(wm * 32 + mt * 16 + (lane & 15)) * 144
                + (uint32_t)(kofs + (lane >> 4) * 8) * 2;
            ldmatrix_x4(a0f[mt], addr);
            ldmatrix_x4(a1f[mt], addr + (GA1 - GA0));
        }
        #pragma unroll
        for (int nt2 = 0; nt2 < 2; nt2++) {
            uint32_t addr = sbase + GB0
                + (uint32_t)(wn * 32 + nt2 * 16 + (lane & 15)) * 144
                + (uint32_t)(kofs + (lane >> 4) * 8) * 2;
            uint32_t t[4];
            ldmatrix_x4(t, addr);
            b0f[nt2 * 2 + 0][0] = t[0]; b0f[nt2 * 2 + 0][1] = t[2];
            b0f[nt2 * 2 + 1][0] = t[1]; b0f[nt2 * 2 + 1][1] = t[3];
            ldmatrix_x4(t, addr + (GB1 - GB0));
            b1f[nt2 * 2 + 0][0] = t[0]; b1f[nt2 * 2 + 0][1] = t[2];
            b1f[nt2 * 2 + 1][0] = t[1]; b1f[nt2 * 2 + 1][1] = t[3];
        }
        #pragma unroll
        for (int mt = 0; mt < 2; mt++)
            #pragma unroll
            for (int nt = 0; nt < 4; nt++) {
                mma_bf16(acc[mt][nt], a0f[mt], b0f[nt]);
                mma_bf16(acc[mt][nt], a0f[mt], b1f[nt]);
                mma_bf16(acc[mt][nt], a1f[mt], b0f[nt]);
            }
    }
}

// ---- projection: q/k -> bf16 split [b][h][s][dh]; v -> transposed [b][h][dh][s]
__global__ void __launch_bounds__(256) proj_mma_kernel(
    const __nv_bfloat16* __restrict__ a_hi, const __nv_bfloat16* __restrict__ a_lo,
    const __nv_bfloat16* __restrict__ w_hi, const __nv_bfloat16* __restrict__ w_lo,
    const float* __restrict__ bias, int which)
{
    extern __shared__ char smem[];
    uint32_t sbase = smem_u32(smem);
    int s0 = blockIdx.x * 128;
    int h  = blockIdx.y;
    int b  = blockIdx.z;
    int tid = threadIdx.x;
    int wid = tid >> 5, lane = tid & 31;
    int wm = wid >> 1, wn = wid & 1;

    float acc[2][4][4];
    #pragma unroll
    for (int mt = 0; mt < 2; mt++)
        #pragma unroll
        for (int nt = 0; nt < 4; nt++)
            #pragma unroll
            for (int e = 0; e < 4; e++) acc[mt][nt][e] = 0.f;

    for (int c = 0; c < 16; c++) {
        __syncthreads();
        int k0 = c * 64;
        #pragma unroll
        for (int i = 0; i < 4; i++) {
            int id = tid + i * 256;
            int m = id >> 3, k8 = id & 7;
            size_t g = ((size_t)(s0 + m) * kB + b) * kD + k0 + k8 * 8;
            *(uint4*)(smem + GA0 + m * 144 + k8 * 16) = *(const uint4*)(a_hi + g);
            *(uint4*)(smem + GA1 + m * 144 + k8 * 16) = *(const uint4*)(a_lo + g);
        }
        #pragma unroll
        for (int i = 0; i < 2; i++) {
            int id = tid + i * 256;
            int n = id >> 3, k8 = id & 7;
            size_t g = ((size_t)h * kDH + n) * kD + k0 + k8 * 8;
            *(uint4*)(smem + GB0 + n * 144 + k8 * 16) = *(const uint4*)(w_hi + g);
            *(uint4*)(smem + GB1 + n * 144 + k8 * 16) = *(const uint4*)(w_lo + g);
        }
        __syncthreads();
        gemm_mainloop_step(sbase, wm, wn, lane, acc);
    }

    int gq = lane >> 2, tg = lane & 3;
    size_t bh = (size_t)b * kH + h;
    if (which < 2) {
        __nv_bfloat16* oh = (which == 0) ? g_qp_hi : g_kp_hi;
        __nv_bfloat16* ol = (which == 0) ? g_qp_lo : g_kp_lo;
        #pragma unroll
        for (int mt = 0; mt < 2; mt++) {
            int row0 = s0 + wm * 32 + mt * 16 + gq;
            #pragma unroll
            for (int nt = 0; nt < 4; nt++) {
                int col = wn * 32 + nt * 8 + tg * 2;
                float b0 = bias[h * kDH + col], b1 = bias[h * kDH + col + 1];
                uint32_t hp, lp;
                size_t off0 = (bh * kS + row0) * kDH + col;
                split_pack(acc[mt][nt][0] + b0, acc[mt][nt][1] + b1, hp, lp);
                *(uint32_t*)(oh + off0) = hp; *(uint32_t*)(ol + off0) = lp;
                split_pack(acc[mt][nt][2] + b0, acc[mt][nt][3] + b1, hp, lp);
                size_t off1 = off0 + (size_t)8 * kDH;
                *(uint32_t*)(oh + off1) = hp; *(uint32_t*)(ol + off1) = lp;
            }
        }
    } else {
        // V transposed: [b][h][dh][s]
        #pragma unroll
        for (int mt = 0; mt < 2; mt++) {
            int row0 = s0 + wm * 32 + mt * 16 + gq;
            #pragma unroll
            for (int nt = 0; nt < 4; nt++) {
                int col = wn * 32 + nt * 8 + tg * 2;
                float b0 = bias[h * kDH + col], b1 = bias[h * kDH + col + 1];
                float vals[4] = {acc[mt][nt][0] + b0, acc[mt][nt][1] + b1,
                                 acc[mt][nt][2] + b0, acc[mt][nt][3] + b1};
                int rr[4] = {row0, row0, row0 + 8, row0 + 8};
                int cc[4] = {col, col + 1, col, col + 1};
                #pragma unroll
                for (int e = 0; e < 4; e++) {
                    __nv_bfloat16 hv = __float2bfloat16_rn(vals[e]);
                    __nv_bfloat16 lv = __float2bfloat16_rn(vals[e] - __bfloat162float(hv));
                    size_t off = (bh * kDH + cc[e]) * kS + rr[e];
                    g_vp_hi[off] = hv;
                    g_vp_lo[off] = lv;
                }
            }
        }
    }
}

// ---- output projection: out[4096,1024] = g_oa @ Wo + bo ----
__global__ void __launch_bounds__(256) outproj_mma_kernel(
    const float* __restrict__ bo, float* __restrict__ out)
{
    extern __shared__ char smem[];
    uint32_t sbase = smem_u32(smem);
    int m0 = blockIdx.x * 128;
    int n0 = blockIdx.y * 64;
    int tid = threadIdx.x;
    int wid = tid >> 5, lane = tid & 31;
    int wm = wid >> 1, wn = wid & 1;

    float acc[2][4][4];
    #pragma unroll
    for (int mt = 0; mt < 2; mt++)
        #pragma unroll
        for (int nt = 0; nt < 4; nt++)
            #pragma unroll
            for (int e = 0; e < 4; e++) acc[mt][nt][e] = 0.f;

    for (int c = 0; c < 16; c++) {
        __syncthreads();
        int k0 = c * 64;
        #pragma unroll
        for (int i = 0; i < 4; i++) {
            int id = tid + i * 256;
            int m = id >> 3, k8 = id & 7;
            size_t g = (size_t)(m0 + m) * kD + k0 + k8 * 8;
            *(uint4*)(smem + GA0 + m * 144 + k8 * 16) = *(const uint4*)(g_oa_hi + g);
            *(uint4*)(smem + GA1 + m * 144 + k8 * 16) = *(const uint4*)(g_oa_lo + g);
        }
        #pragma unroll
        for (int i = 0; i < 2; i++) {
            int id = tid + i * 256;
            int n = id >> 3, k8 = id & 7;
            size_t g = (size_t)(n0 + n) * kD + k0 + k8 * 8;
            *(uint4*)(smem + GB0 + n * 144 + k8 * 16) = *(const uint4*)(g_wo_hi + g);
            *(uint4*)(smem + GB1 + n * 144 + k8 * 16) = *(const uint4*)(g_wo_lo + g);
        }
        __syncthreads();
        gemm_mainloop_step(sbase, wm, wn, lane, acc);
    }

    int gq = lane >> 2, tg = lane & 3;
    #pragma unroll
    for (int mt = 0; mt < 2; mt++) {
        int row = m0 + wm * 32 + mt * 16 + gq;
        #pragma unroll
        for (int nt = 0; nt < 4; nt++) {
            int col = n0 + wn * 32 + nt * 8 + tg * 2;
            float b0 = bo[col], b1 = bo[col + 1];
            size_t r0 = (size_t)row * kD + col;
            *(float2*)(out + r0) = make_float2(acc[mt][nt][0] + b0, acc[mt][nt][1] + b1);
            *(float2*)(out + r0 + 8 * kD) = make_float2(acc[mt][nt][2] + b0, acc[mt][nt][3] + b1);
        }
    }
}

// ===========================================================================
// Tensor-core attention. Per (b,h): 128 q-rows per CTA. 8 warps x 16 rows.
// QK^T and PV via mma.sync, 3-pass bf16 split. P repacked reg->reg (no smem).
// ===========================================================================
#define AK_HI 0
#define AK_LO 9216
#define AV_HI 18432
#define AV_LO 27648
#define AMK   36864
#define ATTN_SMEM (36864 + 256)
#define AQ_LO_STAGE 18432   // Q staging reuses [0, 36864)

__global__ void __launch_bounds__(256) attn_mma_kernel(const int* __restrict__ mask)
{
    extern __shared__ char smem[];
    uint32_t sbase = smem_u32(smem);
    int s0 = blockIdx.x * 128;
    int h  = blockIdx.y;
    int b  = blockIdx.z;
    int tid = threadIdx.x;
    int w = tid >> 5, lane = tid & 31;
    int gq = lane >> 2, tg = lane & 3;
    size_t bh = (size_t)b * kH + h;

    const __nv_bfloat16* qh = g_qp_hi + bh * kS * kDH;
    const __nv_bfloat16* ql = g_qp_lo + bh * kS * kDH;
    const __nv_bfloat16* kh = g_kp_hi + bh * kS * kDH;
    const __nv_bfloat16* kl = g_kp_lo + bh * kS * kDH;
    const __nv_bfloat16* vth = g_vp_hi + bh * kDH * kS;  // [dh][s]
    const __nv_bfloat16* vtl = g_vp_lo + bh * kDH * kS;

    // ---- stage Q tile (128x64 hi/lo) and grab A-frags into registers ----
    #pragma unroll
    for (int i = 0; i < 4; i++) {
        int id = tid + i * 256;
        int row = id >> 3, k8 = id & 7;
        size_t g = (size_t)(s0 + row) * kDH + k8 * 8;
        *(uint4*)(smem + 0 + row * 144 + k8 * 16) = *(const uint4*)(qh + g);
        *(uint4*)(smem + AQ_LO_STAGE + row * 144 + k8 * 16) = *(const uint4*)(ql + g);
    }
    __syncthreads();
    uint32_t qfh[4][4], qfl[4][4];
    #pragma unroll
    for (int ks = 0; ks < 4; ks++) {
        uint32_t addr = sbase + (uint32_t)(w * 16 + (lane & 15)) * 144
                      + (uint32_t)(ks * 16 + (lane >> 4) * 8) * 2;
        ldmatrix_x4(qfh[ks], addr);
        ldmatrix_x4(qfl[ks], addr + AQ_LO_STAGE);
    }

    float acc_o[8][4];
    #pragma unroll
    for (int nt = 0; nt < 8; nt++)
        #pragma unroll
        for (int e = 0; e < 4; e++) acc_o[nt][e] = 0.f;
    float l_run[2] = {0.f, 0.f};
    const float scale = 0.125f;

    for (int j0 = 0; j0 < kS; j0 += 64) {
        __syncthreads();
        // load K (hi/lo) [key][dh] and Vt (hi/lo) [dh][key]
        #pragma unroll
        for (int i = 0; i < 8; i++) {
            int id = tid + (i & 1) * 256;
            int row = id >> 3, k8 = id & 7;
            const __nv_bfloat16* src;
            uint32_t dst;
            if (i < 2)      { src = kh  + (size_t)(j0 + row) * kDH + k8 * 8; dst = AK_HI; }
            else if (i < 4) { src = kl  + (size_t)(j0 + row) * kDH + k8 * 8; dst = AK_LO; }
            else if (i < 6) { src = vth + (size_t)row * kS + j0 + k8 * 8;    dst = AV_HI; }
            else            { src = vtl + (size_t)row * kS + j0 + k8 * 8;    dst = AV_LO; }
            *(uint4*)(smem + dst + row * 144 + k8 * 16) = *(const uint4*)src;
        }
        if (tid < 64)
            ((float*)(smem + AMK))[tid] = (float)mask[(size_t)(j0 + tid) * kB + b] * 1e18f;
        __syncthreads();

        // ---- S = Q K^T (3-pass) ----
        float ps[8][4];
        #pragma unroll
        for (int nt = 0; nt < 8; nt++)
            #pragma unroll
            for (int e = 0; e < 4; e++) ps[nt][e] = 0.f;
        #pragma unroll
        for (int ks = 0; ks < 4; ks++) {
            uint32_t kofs2 = (uint32_t)(ks * 16 + (lane >> 4) * 8) * 2;
            #pragma unroll
            for (int nt2 = 0; nt2 < 4; nt2++) {
                uint32_t addr = sbase + AK_HI + (uint32_t)(nt2 * 16 + (lane & 15)) * 144 + kofs2;
                uint32_t t[4], u[4];
                ldmatrix_x4(t, addr);
                ldmatrix_x4(u, addr + (AK_LO - AK_HI));
                uint32_t bh0[2] = {t[0], t[2]}, bh1[2] = {t[1], t[3]};
                uint32_t bl0[2] = {u[0], u[2]}, bl1[2] = {u[1], u[3]};
                mma_bf16(ps[nt2 * 2 + 0], qfh[ks], bh0);
                mma_bf16(ps[nt2 * 2 + 0], qfh[ks], bl0);
                mma_bf16(ps[nt2 * 2 + 0], qfl[ks], bh0);
                mma_bf16(ps[nt2 * 2 + 1], qfh[ks], bh1);
                mma_bf16(ps[nt2 * 2 + 1], qfh[ks], bl1);
                mma_bf16(ps[nt2 * 2 + 1], qfl[ks], bh1);
            }
        }

        // ---- softmax weights (fp32, no running max; masked -> exactly 0) ----
        const float* Mk = (const float*)(smem + AMK);
        float l0 = 0.f, l1 = 0.f;
        #pragma unroll
        for (int nt = 0; nt < 8; nt++) {
            float mk0 = Mk[nt * 8 + tg * 2], mk1 = Mk[nt * 8 + tg * 2 + 1];
            float p0 = __expf(fminf(ps[nt][0] * scale - mk0, 60.f));
            float p1 = __expf(fminf(ps[nt][1] * scale - mk1, 60.f));
            float p2 = __expf(fminf(ps[nt][2] * scale - mk0, 60.f));
            float p3 = __expf(fminf(ps[nt][3] * scale - mk1, 60.f));
            l0 += p0 + p1; l1 += p2 + p3;
            ps[nt][0] = p0; ps[nt][1] = p1; ps[nt][2] = p2; ps[nt][3] = p3;
        }
        l_run[0] += l0; l_run[1] += l1;

        // ---- O += P V (P split in regs, 3-pass) ----
        #pragma unroll
        for (int ks = 0; ks < 4; ks++) {
            uint32_t pah[4], pal[4];
            split_pack(ps[2 * ks + 0][0], ps[2 * ks + 0][1], pah[0], pal[0]);
            split_pack(ps[2 * ks + 0][2], ps[2 * ks + 0][3], pah[1], pal[1]);
            split_pack(ps[2 * ks + 1][0], ps[2 * ks + 1][1], pah[2], pal[2]);
            split_pack(ps[2 * ks + 1][2], ps[2 * ks + 1][3], pah[3], pal[3]);
            uint32_t kofs2 = (uint32_t)(ks * 16 + (lane >> 4) * 8) * 2;
            #pragma unroll
            for (int nd2 = 0; nd2 < 4; nd2++) {
                uint32_t addr = sbase + AV_HI + (uint32_t)(nd2 * 16 + (lane & 15)) * 144 + kofs2;
                uint32_t t[4], u[4];
                ldmatrix_x4(t, addr);
                ldmatrix_x4(u, addr + (AV_LO - AV_HI));
                uint32_t bh0[2] = {t[0], t[2]}, bh1[2] = {t[1], t[3]};
                uint32_t bl0[2] = {u[0], u[2]}, bl1[2] = {u[1], u[3]};
                mma_bf16(acc_o[nd2 * 2 + 0], pah, bh0);
                mma_bf16(acc_o[nd2 * 2 + 0], pah, bl0);
                mma_bf16(acc_o[nd2 * 2 + 0], pal, bh0);
                mma_bf16(acc_o[nd2 * 2 + 1], pah, bh1);
                mma_bf16(acc_o[nd2 * 2 + 1], pah, bl1);
                mma_bf16(acc_o[nd2 * 2 + 1], pal, bh1);
            }
        }
    }

    // ---- normalize and write bf16-split concat output ----
    #pragma unroll
    for (int off = 1; off <= 2; off <<= 1) {
        l_run[0] += __shfl_xor_sync(0xffffffffu, l_run[0], off);
        l_run[1] += __shfl_xor_sync(0xffffffffu, l_run[1], off);
    }
    float inv0 = 1.0f / l_run[0], inv1 = 1.0f / l_run[1];

    int srow = s0 + w * 16 + gq;
    size_t m0r = ((size_t)srow * kB + b) * kD + (size_t)h * kDH;
    size_t m1r = ((size_t)(srow + 8) * kB + b) * kD + (size_t)h * kDH;
    #pragma unroll
    for (int nt = 0; nt < 8; nt++) {
        int col = nt * 8 + tg * 2;
        uint32_t hp, lp;
        split_pack(acc_o[nt][0] * inv0, acc_o[nt][1] * inv0, hp, lp);
        *(uint32_t*)(g_oa_hi + m0r + col) = hp;
        *(uint32_t*)(g_oa_lo + m0r + col) = lp;
        split_pack(acc_o[nt][2] * inv1, acc_o[nt][3] * inv1, hp, lp);
        *(uint32_t*)(g_oa_hi + m1r + col) = hp;
        *(uint32_t*)(g_oa_lo + m1r + col) = lp;
    }
}

// ---------------------------------------------------------------------------
extern "C" void kernel_launch(void* const* d_in, const int* in_sizes, int n_in,
                              void* d_out, int out_size) {
    (void)in_sizes; (void)n_in; (void)out_size;
    const float* query = (const float*)d_in[0];
    const float* key   = (const float*)d_in[1];
    const float* value = (const float*)d_in[2];
    const int*   kmask = (const int*)  d_in[3];
    const float* Wq    = (const float*)d_in[4];
    const float* bq    = (const float*)d_in[5];
    const float* Wk    = (const float*)d_in[6];
    const float* bk    = (const float*)d_in[7];
    const float* Wv    = (const float*)d_in[8];
    const float* bvp   = (const float*)d_in[9];
    const float* Wo    = (const float*)d_in[10];
    const float* bo    = (const float*)d_in[11];
    float* out = (float*)d_out;

    cudaFuncSetAttribute(proj_mma_kernel, cudaFuncAttributeMaxDynamicSharedMemorySize, GEMM_SMEM);
    cudaFuncSetAttribute(outproj_mma_kernel, cudaFuncAttributeMaxDynamicSharedMemorySize, GEMM_SMEM);
    cudaFuncSetAttribute(attn_mma_kernel, cudaFuncAttributeMaxDynamicSharedMemorySize, ATTN_SMEM);

    __nv_bfloat16 *qa_hi, *qa_lo, *ka_hi, *ka_lo, *va_hi, *va_lo;
    __nv_bfloat16 *wq_hi, *wq_lo, *wk_hi, *wk_lo, *wv_hi, *wv_lo, *wo_hi, *wo_lo;
    cudaGetSymbolAddress((void**)&qa_hi, g_qa_hi); cudaGetSymbolAddress((void**)&qa_lo, g_qa_lo);
    cudaGetSymbolAddress((void**)&ka_hi, g_ka_hi); cudaGetSymbolAddress((void**)&ka_lo, g_ka_lo);
    cudaGetSymbolAddress((void**)&va_hi, g_va_hi); cudaGetSymbolAddress((void**)&va_lo, g_va_lo);
    cudaGetSymbolAddress((void**)&wq_hi, g_wq_hi); cudaGetSymbolAddress((void**)&wq_lo, g_wq_lo);
    cudaGetSymbolAddress((void**)&wk_hi, g_wk_hi); cudaGetSymbolAddress((void**)&wk_lo, g_wk_lo);
    cudaGetSymbolAddress((void**)&wv_hi, g_wv_hi); cudaGetSymbolAddress((void**)&wv_lo, g_wv_lo);
    cudaGetSymbolAddress((void**)&wo_hi, g_wo_hi); cudaGetSymbolAddress((void**)&wo_lo, g_wo_lo);

    const int n4_act = kS * kB * kD / 4;

    split_kernel<<<n4_act / 256, 256>>>(query, qa_hi, qa_lo, n4_act);
    split_kernel<<<n4_act / 256, 256>>>(key,   ka_hi, ka_lo, n4_act);
    split_kernel<<<n4_act / 256, 256>>>(value, va_hi, va_lo, n4_act);

    transpose_split_kernel<<<dim3(kDH / 32, kD / 32, kH), dim3(32, 8)>>>(Wq, wq_hi, wq_lo, kD, kDH);
    transpose_split_kernel<<<dim3(kDH / 32, kD / 32, kH), dim3(32, 8)>>>(Wk, wk_hi, wk_lo, kD, kDH);
    transpose_split_kernel<<<dim3(kDH / 32, kD / 32, kH), dim3(32, 8)>>>(Wv, wv_hi, wv_lo, kD, kDH);
    transpose_split_kernel<<<dim3(kD / 32, kD / 32, 1), dim3(32, 8)>>>(Wo, wo_hi, wo_lo, kD, kD);

    dim3 pg(kS / 128, kH, kB);
    proj_mma_kernel<<<pg, 256, GEMM_SMEM>>>(qa_hi, qa_lo, wq_hi, wq_lo, bq, 0);
    proj_mma_kernel<<<pg, 256, GEMM_SMEM>>>(ka_hi, ka_lo, wk_hi, wk_lo, bk, 1);
    proj_mma_kernel<<<pg, 256, GEMM_SMEM>>>(va_hi, va_lo, wv_hi, wv_lo, bvp, 2);

    attn_mma_kernel<<<dim3(kS / 128, kH, kB), 256, ATTN_SMEM>>>(kmask);

    outproj_mma_kernel<<<dim3((kS * kB) / 128, kD / 64), 256, GEMM_SMEM>>>(bo, out);
}

// round 8
// speedup vs baseline: 2.6146x; 1.1449x over previous
#include <cuda_runtime.h>
#include <cuda_bf16.h>
#include <math.h>
#include <cstdint>

#define kS  1024
#define kB  4
#define kD  1024
#define kH  16
#define kDH 64

// bf16 split scratch (hi + residual-lo)
__device__ __nv_bfloat16 g_qa_hi[kS*kB*kD], g_qa_lo[kS*kB*kD];   // activations
__device__ __nv_bfloat16 g_ka_hi[kS*kB*kD], g_ka_lo[kS*kB*kD];
__device__ __nv_bfloat16 g_va_hi[kS*kB*kD], g_va_lo[kS*kB*kD];
__device__ __nv_bfloat16 g_oa_hi[kS*kB*kD], g_oa_lo[kS*kB*kD];   // attn out (concat)
__device__ __nv_bfloat16 g_wq_hi[kH*kDH*kD], g_wq_lo[kH*kDH*kD]; // [h][n][k]
__device__ __nv_bfloat16 g_wk_hi[kH*kDH*kD], g_wk_lo[kH*kDH*kD];
__device__ __nv_bfloat16 g_wv_hi[kH*kDH*kD], g_wv_lo[kH*kDH*kD];
__device__ __nv_bfloat16 g_wo_hi[kD*kD],     g_wo_lo[kD*kD];     // [n][k]
// projected q/k/v in bf16 split
__device__ __nv_bfloat16 g_qp_hi[kB*kH*kS*kDH], g_qp_lo[kB*kH*kS*kDH]; // [b][h][s][dh]
__device__ __nv_bfloat16 g_kp_hi[kB*kH*kS*kDH], g_kp_lo[kB*kH*kS*kDH]; // [b][h][s][dh]
__device__ __nv_bfloat16 g_vp_hi[kB*kH*kS*kDH], g_vp_lo[kB*kH*kS*kDH]; // [b][h][dh][s]

// ===================== helpers =====================
__device__ __forceinline__ uint32_t smem_u32(const void* p) {
    uint32_t a;
    asm("{ .reg .u64 t; cvta.to.shared.u64 t, %1; cvt.u32.u64 %0, t; }" : "=r"(a) : "l"(p));
    return a;
}
__device__ __forceinline__ void ldmatrix_x4(uint32_t* r, uint32_t a) {
    asm volatile("ldmatrix.sync.aligned.m8n8.x4.shared.b16 {%0,%1,%2,%3}, [%4];"
        : "=r"(r[0]), "=r"(r[1]), "=r"(r[2]), "=r"(r[3]) : "r"(a));
}
__device__ __forceinline__ void mma_bf16(float* c, const uint32_t* a, const uint32_t* b) {
    asm volatile("mma.sync.aligned.m16n8k16.row.col.f32.bf16.bf16.f32 "
        "{%0,%1,%2,%3},{%4,%5,%6,%7},{%8,%9},{%0,%1,%2,%3};"
        : "+f"(c[0]), "+f"(c[1]), "+f"(c[2]), "+f"(c[3])
        : "r"(a[0]), "r"(a[1]), "r"(a[2]), "r"(a[3]), "r"(b[0]), "r"(b[1]));
}
__device__ __forceinline__ void split_pack(float x, float y, uint32_t& hp, uint32_t& lp) {
    __nv_bfloat16 hx = __float2bfloat16_rn(x);
    __nv_bfloat16 hy = __float2bfloat16_rn(y);
    __nv_bfloat16 lx = __float2bfloat16_rn(x - __bfloat162float(hx));
    __nv_bfloat16 ly = __float2bfloat16_rn(y - __bfloat162float(hy));
    hp = (uint32_t)__bfloat16_as_ushort(hx) | ((uint32_t)__bfloat16_as_ushort(hy) << 16);
    lp = (uint32_t)__bfloat16_as_ushort(lx) | ((uint32_t)__bfloat16_as_ushort(ly) << 16);
}
__device__ __forceinline__ void cp_async16(uint32_t saddr, const void* gptr) {
    asm volatile("cp.async.cg.shared.global [%0], [%1], 16;" :: "r"(saddr), "l"(gptr));
}
#define CP_COMMIT() asm volatile("cp.async.commit_group;" ::: "memory")
#define CP_WAIT_1() asm volatile("cp.async.wait_group 1;" ::: "memory")
#define CP_WAIT_0() asm volatile("cp.async.wait_group 0;" ::: "memory")

// ===========================================================================
// Prep 1: split q/k/v activations in one launch. grid (n4/256, 3)
// ===========================================================================
__global__ void __launch_bounds__(256) split3_kernel(
    const float* __restrict__ q, const float* __restrict__ k,
    const float* __restrict__ v, int n4)
{
    int which = blockIdx.y;
    const float* src = (which == 0) ? q : (which == 1) ? k : v;
    __nv_bfloat16* hi = (which == 0) ? g_qa_hi : (which == 1) ? g_ka_hi : g_va_hi;
    __nv_bfloat16* lo = (which == 0) ? g_qa_lo : (which == 1) ? g_ka_lo : g_va_lo;
    int i = blockIdx.x * blockDim.x + threadIdx.x;
    if (i >= n4) return;
    float4 vv = ((const float4*)src)[i];
    uint32_t h0, l0, h1, l1;
    split_pack(vv.x, vv.y, h0, l0);
    split_pack(vv.z, vv.w, h1, l1);
    *(uint2*)(hi + (size_t)i * 4) = make_uint2(h0, h1);
    *(uint2*)(lo + (size_t)i * 4) = make_uint2(l0, l1);
}

// ===========================================================================
// Prep 2: transpose+split Wq/Wk/Wv [h][D][DH] -> [h][DH][D]. grid (2,32,48)
// ===========================================================================
__global__ void __launch_bounds__(256) transpose_wqkv_kernel(
    const float* __restrict__ Wq, const float* __restrict__ Wk,
    const float* __restrict__ Wv)
{
    __shared__ float tile[32][33];
    int which = blockIdx.z >> 4;
    int h = blockIdx.z & 15;
    const float* src = ((which == 0) ? Wq : (which == 1) ? Wk : Wv) + (size_t)h * kD * kDH;
    __nv_bfloat16* hi = ((which == 0) ? g_wq_hi : (which == 1) ? g_wk_hi : g_wv_hi) + (size_t)h * kDH * kD;
    __nv_bfloat16* lo = ((which == 0) ? g_wq_lo : (which == 1) ? g_wk_lo : g_wv_lo) + (size_t)h * kDH * kD;
    int c0 = blockIdx.x * 32, r0 = blockIdx.y * 32;
    int tx = threadIdx.x, ty = threadIdx.y;
    #pragma unroll
    for (int i = 0; i < 4; i++)
        tile[ty + i * 8][tx] = src[(size_t)(r0 + ty + i * 8) * kDH + c0 + tx];
    __syncthreads();
    #pragma unroll
    for (int i = 0; i < 4; i++) {
        float v = tile[tx][ty + i * 8];
        __nv_bfloat16 hv = __float2bfloat16_rn(v);
        __nv_bfloat16 lv = __float2bfloat16_rn(v - __bfloat162float(hv));
        size_t o = (size_t)(c0 + ty + i * 8) * kD + r0 + tx;
        hi[o] = hv;
        lo[o] = lv;
    }
}

// Wo [D][D] -> [n][k]. grid (32,32)
__global__ void __launch_bounds__(256) transpose_wo_kernel(const float* __restrict__ Wo)
{
    __shared__ float tile[32][33];
    int c0 = blockIdx.x * 32, r0 = blockIdx.y * 32;
    int tx = threadIdx.x, ty = threadIdx.y;
    #pragma unroll
    for (int i = 0; i < 4; i++)
        tile[ty + i * 8][tx] = Wo[(size_t)(r0 + ty + i * 8) * kD + c0 + tx];
    __syncthreads();
    #pragma unroll
    for (int i = 0; i < 4; i++) {
        float v = tile[tx][ty + i * 8];
        __nv_bfloat16 hv = __float2bfloat16_rn(v);
        __nv_bfloat16 lv = __float2bfloat16_rn(v - __bfloat162float(hv));
        size_t o = (size_t)(c0 + ty + i * 8) * kD + r0 + tx;
        g_wo_hi[o] = hv;
        g_wo_lo[o] = lv;
    }
}

// ===========================================================================
// mma.sync GEMM, 2-stage cp.async pipeline. BM=128, BN=64, BK=64, 256 thr.
// Stage layout: A_hi 0, A_lo 18432, B_hi 36864, B_lo 46080; stage size 55296.
// ===========================================================================
#define SA0 0
#define SA1 18432
#define SB0 36864
#define SB1 46080
#define STG_SZ 55296
#define GEMM_SMEM (2 * STG_SZ)   // 110592

__device__ __forceinline__ void gemm_compute_chunk(
    uint32_t stb, int wm, int wn, int lane, float acc[2][4][4])
{
    #pragma unroll
    for (int ks = 0; ks < 4; ks++) {
        int kofs = ks * 16;
        uint32_t a0f[2][4], a1f[2][4], b0f[4][2], b1f[4][2];
        #pragma unroll
        for (int mt = 0; mt < 2; mt++) {
            uint32_t addr = stb + SA0
                + (uint32_t)(wm * 32 + mt * 16 + (lane & 15)) * 144
                + (uint32_t)(kofs + (lane >> 4) * 8) * 2;
            ldmatrix_x4(a0f[mt], addr);
            ldmatrix_x4(a1f[mt], addr + (SA1 - SA0));
        }
        #pragma unroll
        for (int nt2 = 0; nt2 < 2; nt2++) {
            uint32_t addr = stb + SB0
                + (uint32_t)(wn * 32 + nt2 * 16 + (lane & 15)) * 144
                + (uint32_t)(kofs + (lane >> 4) * 8) * 2;
            uint32_t t[4];
            ldmatrix_x4(t, addr);
            b0f[nt2 * 2 + 0][0] = t[0]; b0f[nt2 * 2 + 0][1] = t[2];
            b0f[nt2 * 2 + 1][0] = t[1]; b0f[nt2 * 2 + 1][1] = t[3];
            ldmatrix_x4(t, addr + (SB1 - SB0));
            b1f[nt2 * 2 + 0][0] = t[0]; b1f[nt2 * 2 + 0][1] = t[2];
            b1f[nt2 * 2 + 1][0] = t[1]; b1f[nt2 * 2 + 1][1] = t[3];
        }
        #pragma unroll
        for (int mt = 0; mt < 2; mt++)
            #pragma unroll
            for (int nt = 0; nt < 4; nt++) {
                mma_bf16(acc[mt][nt], a0f[mt], b0f[nt]);
                mma_bf16(acc[mt][nt], a0f[mt], b1f[nt]);
                mma_bf16(acc[mt][nt], a1f[mt], b0f[nt]);
            }
    }
}

// ---- fused projections. grid (8, 48, 4): y -> which*16+h ----
__global__ void __launch_bounds__(256) proj_mma_kernel(
    const float* __restrict__ bq, const float* __restrict__ bk,
    const float* __restrict__ bv)
{
    extern __shared__ char smem[];
    uint32_t sbase = smem_u32(smem);
    int s0 = blockIdx.x * 128;
    int which = blockIdx.y >> 4;
    int h  = blockIdx.y & 15;
    int b  = blockIdx.z;
    int tid = threadIdx.x;
    int wid = tid >> 5, lane = tid & 31;
    int wm = wid >> 1, wn = wid & 1;

    const __nv_bfloat16* a_hi = (which == 0) ? g_qa_hi : (which == 1) ? g_ka_hi : g_va_hi;
    const __nv_bfloat16* a_lo = (which == 0) ? g_qa_lo : (which == 1) ? g_ka_lo : g_va_lo;
    const __nv_bfloat16* w_hi = (which == 0) ? g_wq_hi : (which == 1) ? g_wk_hi : g_wv_hi;
    const __nv_bfloat16* w_lo = (which == 0) ? g_wq_lo : (which == 1) ? g_wk_lo : g_wv_lo;
    const float* bias = (which == 0) ? bq : (which == 1) ? bk : bv;

    float acc[2][4][4];
    #pragma unroll
    for (int mt = 0; mt < 2; mt++)
        #pragma unroll
        for (int nt = 0; nt < 4; nt++)
            #pragma unroll
            for (int e = 0; e < 4; e++) acc[mt][nt][e] = 0.f;

    auto load_chunk = [&](int c, int stg) {
        uint32_t stb = sbase + stg * STG_SZ;
        int k0 = c * 64;
        #pragma unroll
        for (int i = 0; i < 4; i++) {
            int id = tid + i * 256;
            int m = id >> 3, k8 = id & 7;
            size_t g = ((size_t)(s0 + m) * kB + b) * kD + k0 + k8 * 8;
            uint32_t d = stb + m * 144 + k8 * 16;
            cp_async16(d + SA0, a_hi + g);
            cp_async16(d + SA1, a_lo + g);
        }
        #pragma unroll
        for (int i = 0; i < 2; i++) {
            int id = tid + i * 256;
            int n = id >> 3, k8 = id & 7;
            size_t g = ((size_t)h * kDH + n) * kD + k0 + k8 * 8;
            uint32_t d = stb + n * 144 + k8 * 16;
            cp_async16(d + SB0, w_hi + g);
            cp_async16(d + SB1, w_lo + g);
        }
    };

    load_chunk(0, 0);
    CP_COMMIT();
    for (int c = 0; c < 16; c++) {
        if (c < 15) {
            load_chunk(c + 1, (c + 1) & 1);
            CP_COMMIT();
            CP_WAIT_1();
        } else {
            CP_WAIT_0();
        }
        __syncthreads();
        gemm_compute_chunk(sbase + (c & 1) * STG_SZ, wm, wn, lane, acc);
        __syncthreads();
    }

    int gq = lane >> 2, tg = lane & 3;
    size_t bh = (size_t)b * kH + h;
    if (which < 2) {
        __nv_bfloat16* oh = (which == 0) ? g_qp_hi : g_kp_hi;
        __nv_bfloat16* ol = (which == 0) ? g_qp_lo : g_kp_lo;
        #pragma unroll
        for (int mt = 0; mt < 2; mt++) {
            int row0 = s0 + wm * 32 + mt * 16 + gq;
            #pragma unroll
            for (int nt = 0; nt < 4; nt++) {
                int col = wn * 32 + nt * 8 + tg * 2;
                float b0 = bias[h * kDH + col], b1 = bias[h * kDH + col + 1];
                uint32_t hp, lp;
                size_t off0 = (bh * kS + row0) * kDH + col;
                split_pack(acc[mt][nt][0] + b0, acc[mt][nt][1] + b1, hp, lp);
                *(uint32_t*)(oh + off0) = hp; *(uint32_t*)(ol + off0) = lp;
                split_pack(acc[mt][nt][2] + b0, acc[mt][nt][3] + b1, hp, lp);
                size_t off1 = off0 + (size_t)8 * kDH;
                *(uint32_t*)(oh + off1) = hp; *(uint32_t*)(ol + off1) = lp;
            }
        }
    } else {
        #pragma unroll
        for (int mt = 0; mt < 2; mt++) {
            int row0 = s0 + wm * 32 + mt * 16 + gq;
            #pragma unroll
            for (int nt = 0; nt < 4; nt++) {
                int col = wn * 32 + nt * 8 + tg * 2;
                float b0 = bias[h * kDH + col], b1 = bias[h * kDH + col + 1];
                float vals[4] = {acc[mt][nt][0] + b0, acc[mt][nt][1] + b1,
                                 acc[mt][nt][2] + b0, acc[mt][nt][3] + b1};
                int rr[4] = {row0, row0, row0 + 8, row0 + 8};
                int cc[4] = {col, col + 1, col, col + 1};
                #pragma unroll
                for (int e = 0; e < 4; e++) {
                    __nv_bfloat16 hv = __float2bfloat16_rn(vals[e]);
                    __nv_bfloat16 lv = __float2bfloat16_rn(vals[e] - __bfloat162float(hv));
                    size_t off = (bh * kDH + cc[e]) * kS + rr[e];
                    g_vp_hi[off] = hv;
                    g_vp_lo[off] = lv;
                }
            }
        }
    }
}

// ---- output projection ----
__global__ void __launch_bounds__(256) outproj_mma_kernel(
    const float* __restrict__ bo, float* __restrict__ out)
{
    extern __shared__ char smem[];
    uint32_t sbase = smem_u32(smem);
    int m0 = blockIdx.x * 128;
    int n0 = blockIdx.y * 64;
    int tid = threadIdx.x;
    int wid = tid >> 5, lane = tid & 31;
    int wm = wid >> 1, wn = wid & 1;

    float acc[2][4][4];
    #pragma unroll
    for (int mt = 0; mt < 2; mt++)
        #pragma unroll
        for (int nt = 0; nt < 4; nt++)
            #pragma unroll
            for (int e = 0; e < 4; e++) acc[mt][nt][e] = 0.f;

    auto load_chunk = [&](int c, int stg) {
        uint32_t stb = sbase + stg * STG_SZ;
        int k0 = c * 64;
        #pragma unroll
        for (int i = 0; i < 4; i++) {
            int id = tid + i * 256;
            int m = id >> 3, k8 = id & 7;
            size_t g = (size_t)(m0 + m) * kD + k0 + k8 * 8;
            uint32_t d = stb + m * 144 + k8 * 16;
            cp_async16(d + SA0, g_oa_hi + g);
            cp_async16(d + SA1, g_oa_lo + g);
        }
        #pragma unroll
        for (int i = 0; i < 2; i++) {
            int id = tid + i * 256;
            int n = id >> 3, k8 = id & 7;
            size_t g = (size_t)(n0 + n) * kD + k0 + k8 * 8;
            uint32_t d = stb + n * 144 + k8 * 16;
            cp_async16(d + SB0, g_wo_hi + g);
            cp_async16(d + SB1, g_wo_lo + g);
        }
    };

    load_chunk(0, 0);
    CP_COMMIT();
    for (int c = 0; c < 16; c++) {
        if (c < 15) {
            load_chunk(c + 1, (c + 1) & 1);
            CP_COMMIT();
            CP_WAIT_1();
        } else {
            CP_WAIT_0();
        }
        __syncthreads();
        gemm_compute_chunk(sbase + (c & 1) * STG_SZ, wm, wn, lane, acc);
        __syncthreads();
    }

    int gq = lane >> 2, tg = lane & 3;
    #pragma unroll
    for (int mt = 0; mt < 2; mt++) {
        int row = m0 + wm * 32 + mt * 16 + gq;
        #pragma unroll
        for (int nt = 0; nt < 4; nt++) {
            int col = n0 + wn * 32 + nt * 8 + tg * 2;
            float b0 = bo[col], b1 = bo[col + 1];
            size_t r0 = (size_t)row * kD + col;
            *(float2*)(out + r0) = make_float2(acc[mt][nt][0] + b0, acc[mt][nt][1] + b1);
            *(float2*)(out + r0 + 8 * kD) = make_float2(acc[mt][nt][2] + b0, acc[mt][nt][3] + b1);
        }
    }
}

// ===========================================================================
// Tensor-core attention with 2-stage cp.async K/V pipeline + mask preload.
// Stage: K_hi 0, K_lo 9216, V_hi 18432, V_lo 27648; stage size 36864.
// Mask (1024 floats) at 73728. Q staged into stage 0 before mainloop.
// ===========================================================================
#define AK_HI 0
#define AK_LO 9216
#define AV_HI 18432
#define AV_LO 27648
#define ASTG  36864
#define AMK   73728
#define ATTN_SMEM (73728 + 4096)

__global__ void __launch_bounds__(256) attn_mma_kernel(const int* __restrict__ mask)
{
    extern __shared__ char smem[];
    uint32_t sbase = smem_u32(smem);
    int s0 = blockIdx.x * 128;
    int h  = blockIdx.y;
    int b  = blockIdx.z;
    int tid = threadIdx.x;
    int w = tid >> 5, lane = tid & 31;
    int gq = lane >> 2, tg = lane & 3;
    size_t bh = (size_t)b * kH + h;

    const __nv_bfloat16* qh = g_qp_hi + bh * kS * kDH;
    const __nv_bfloat16* ql = g_qp_lo + bh * kS * kDH;
    const __nv_bfloat16* kh = g_kp_hi + bh * kS * kDH;
    const __nv_bfloat16* kl = g_kp_lo + bh * kS * kDH;
    const __nv_bfloat16* vth = g_vp_hi + bh * kDH * kS;  // [dh][s]
    const __nv_bfloat16* vtl = g_vp_lo + bh * kDH * kS;

    // ---- mask preload (whole column b) ----
    float* Mk = (float*)(smem + AMK);
    for (int idx = tid; idx < kS; idx += 256)
        Mk[idx] = (float)mask[(size_t)idx * kB + b] * 1e18f;

    // ---- stage Q tile (128x64 hi/lo) into stage 0 and grab A-frags ----
    #pragma unroll
    for (int i = 0; i < 4; i++) {
        int id = tid + i * 256;
        int row = id >> 3, k8 = id & 7;
        size_t g = (size_t)(s0 + row) * kDH + k8 * 8;
        cp_async16(sbase + 0 + row * 144 + k8 * 16, qh + g);
        cp_async16(sbase + 18432 + row * 144 + k8 * 16, ql + g);
    }
    CP_COMMIT();
    CP_WAIT_0();
    __syncthreads();
    uint32_t qfh[4][4], qfl[4][4];
    #pragma unroll
    for (int ks = 0; ks < 4; ks++) {
        uint32_t addr = sbase + (uint32_t)(w * 16 + (lane & 15)) * 144
                      + (uint32_t)(ks * 16 + (lane >> 4) * 8) * 2;
        ldmatrix_x4(qfh[ks], addr);
        ldmatrix_x4(qfl[ks], addr + 18432);
    }
    __syncthreads();  // all warps done reading Q before stage 0 reuse

    float acc_o[8][4];
    #pragma unroll
    for (int nt = 0; nt < 8; nt++)
        #pragma unroll
        for (int e = 0; e < 4; e++) acc_o[nt][e] = 0.f;
    float l_run[2] = {0.f, 0.f};
    const float scale = 0.125f;

    auto load_tile = [&](int t, int stg) {
        uint32_t stb = sbase + stg * ASTG;
        int j0 = t * 64;
        #pragma unroll
        for (int i = 0; i < 8; i++) {
            int id = tid + (i & 1) * 256;
            int row = id >> 3, k8 = id & 7;
            const __nv_bfloat16* src;
            uint32_t dst;
            if (i < 2)      { src = kh  + (size_t)(j0 + row) * kDH + k8 * 8; dst = AK_HI; }
            else if (i < 4) { src = kl  + (size_t)(j0 + row) * kDH + k8 * 8; dst = AK_LO; }
            else if (i < 6) { src = vth + (size_t)row * kS + j0 + k8 * 8;    dst = AV_HI; }
            else            { src = vtl + (size_t)row * kS + j0 + k8 * 8;    dst = AV_LO; }
            cp_async16(stb + dst + row * 144 + k8 * 16, src);
        }
    };

    load_tile(0, 0);
    CP_COMMIT();
    for (int t = 0; t < 16; t++) {
        if (t < 15) {
            load_tile(t + 1, (t + 1) & 1);
            CP_COMMIT();
            CP_WAIT_1();
        } else {
            CP_WAIT_0();
        }
        __syncthreads();
        uint32_t stb = sbase + (t & 1) * ASTG;
        int j0 = t * 64;

        // ---- S = Q K^T (3-pass) ----
        float ps[8][4];
        #pragma unroll
        for (int nt = 0; nt < 8; nt++)
            #pragma unroll
            for (int e = 0; e < 4; e++) ps[nt][e] = 0.f;
        #pragma unroll
        for (int ks = 0; ks < 4; ks++) {
            uint32_t kofs2 = (uint32_t)(ks * 16 + (lane >> 4) * 8) * 2;
            #pragma unroll
            for (int nt2 = 0; nt2 < 4; nt2++) {
                uint32_t addr = stb + AK_HI + (uint32_t)(nt2 * 16 + (lane & 15)) * 144 + kofs2;
                uint32_t tt[4], u[4];
                ldmatrix_x4(tt, addr);
                ldmatrix_x4(u, addr + (AK_LO - AK_HI));
                uint32_t bh0[2] = {tt[0], tt[2]}, bh1[2] = {tt[1], tt[3]};
                uint32_t bl0[2] = {u[0], u[2]}, bl1[2] = {u[1], u[3]};
                mma_bf16(ps[nt2 * 2 + 0], qfh[ks], bh0);
                mma_bf16(ps[nt2 * 2 + 0], qfh[ks], bl0);
                mma_bf16(ps[nt2 * 2 + 0], qfl[ks], bh0);
                mma_bf16(ps[nt2 * 2 + 1], qfh[ks], bh1);
                mma_bf16(ps[nt2 * 2 + 1], qfh[ks], bl1);
                mma_bf16(ps[nt2 * 2 + 1], qfl[ks], bh1);
            }
        }

        // ---- softmax weights ----
        float l0 = 0.f, l1 = 0.f;
        #pragma unroll
        for (int nt = 0; nt < 8; nt++) {
            float mk0 = Mk[j0 + nt * 8 + tg * 2], mk1 = Mk[j0 + nt * 8 + tg * 2 + 1];
            float p0 = __expf(fminf(ps[nt][0] * scale - mk0, 60.f));
            float p1 = __expf(fminf(ps[nt][1] * scale - mk1, 60.f));
            float p2 = __expf(fminf(ps[nt][2] * scale - mk0, 60.f));
            float p3 = __expf(fminf(ps[nt][3] * scale - mk1, 60.f));
            l0 += p0 + p1; l1 += p2 + p3;
            ps[nt][0] = p0; ps[nt][1] = p1; ps[nt][2] = p2; ps[nt][3] = p3;
        }
        l_run[0] += l0; l_run[1] += l1;

        // ---- O += P V (P split in regs, 3-pass) ----
        #pragma unroll
        for (int ks = 0; ks < 4; ks++) {
            uint32_t pah[4], pal[4];
            split_pack(ps[2 * ks + 0][0], ps[2 * ks + 0][1], pah[0], pal[0]);
            split_pack(ps[2 * ks + 0][2], ps[2 * ks + 0][3], pah[1], pal[1]);
            split_pack(ps[2 * ks + 1][0], ps[2 * ks + 1][1], pah[2], pal[2]);
            split_pack(ps[2 * ks + 1][2], ps[2 * ks + 1][3], pah[3], pal[3]);
            uint32_t kofs2 = (uint32_t)(ks * 16 + (lane >> 4) * 8) * 2;
            #pragma unroll
            for (int nd2 = 0; nd2 < 4; nd2++) {
                uint32_t addr = stb + AV_HI + (uint32_t)(nd2 * 16 + (lane & 15)) * 144 + kofs2;
                uint32_t tt[4], u[4];
                ldmatrix_x4(tt, addr);
                ldmatrix_x4(u, addr + (AV_LO - AV_HI));
                uint32_t bh0[2] = {tt[0], tt[2]}, bh1[2] = {tt[1], tt[3]};
                uint32_t bl0[2] = {u[0], u[2]}, bl1[2] = {u[1], u[3]};
                mma_bf16(acc_o[nd2 * 2 + 0], pah, bh0);
                mma_bf16(acc_o[nd2 * 2 + 0], pah, bl0);
                mma_bf16(acc_o[nd2 * 2 + 0], pal, bh0);
                mma_bf16(acc_o[nd2 * 2 + 1], pah, bh1);
                mma_bf16(acc_o[nd2 * 2 + 1], pah, bl1);
                mma_bf16(acc_o[nd2 * 2 + 1], pal, bh1);
            }
        }
        __syncthreads();
    }

    // ---- normalize and write bf16-split concat output ----
    #pragma unroll
    for (int off = 1; off <= 2; off <<= 1) {
        l_run[0] += __shfl_xor_sync(0xffffffffu, l_run[0], off);
        l_run[1] += __shfl_xor_sync(0xffffffffu, l_run[1], off);
    }
    float inv0 = 1.0f / l_run[0], inv1 = 1.0f / l_run[1];

    int srow = s0 + w * 16 + gq;
    size_t m0r = ((size_t)srow * kB + b) * kD + (size_t)h * kDH;
    size_t m1r = ((size_t)(srow + 8) * kB + b) * kD + (size_t)h * kDH;
    #pragma unroll
    for (int nt = 0; nt < 8; nt++) {
        int col = nt * 8 + tg * 2;
        uint32_t hp, lp;
        split_pack(acc_o[nt][0] * inv0, acc_o[nt][1] * inv0, hp, lp);
        *(uint32_t*)(g_oa_hi + m0r + col) = hp;
        *(uint32_t*)(g_oa_lo + m0r + col) = lp;
        split_pack(acc_o[nt][2] * inv1, acc_o[nt][3] * inv1, hp, lp);
        *(uint32_t*)(g_oa_hi + m1r + col) = hp;
        *(uint32_t*)(g_oa_lo + m1r + col) = lp;
    }
}

// ---------------------------------------------------------------------------
extern "C" void kernel_launch(void* const* d_in, const int* in_sizes, int n_in,
                              void* d_out, int out_size) {
    (void)in_sizes; (void)n_in; (void)out_size;
    const float* query = (const float*)d_in[0];
    const float* key   = (const float*)d_in[1];
    const float* value = (const float*)d_in[2];
    const int*   kmask = (const int*)  d_in[3];
    const float* Wq    = (const float*)d_in[4];
    const float* bq    = (const float*)d_in[5];
    const float* Wk    = (const float*)d_in[6];
    const float* bk    = (const float*)d_in[7];
    const float* Wv    = (const float*)d_in[8];
    const float* bvp   = (const float*)d_in[9];
    const float* Wo    = (const float*)d_in[10];
    const float* bo    = (const float*)d_in[11];
    float* out = (float*)d_out;

    cudaFuncSetAttribute(proj_mma_kernel, cudaFuncAttributeMaxDynamicSharedMemorySize, GEMM_SMEM);
    cudaFuncSetAttribute(outproj_mma_kernel, cudaFuncAttributeMaxDynamicSharedMemorySize, GEMM_SMEM);
    cudaFuncSetAttribute(attn_mma_kernel, cudaFuncAttributeMaxDynamicSharedMemorySize, ATTN_SMEM);

    const int n4_act = kS * kB * kD / 4;

    split3_kernel<<<dim3(n4_act / 256, 3), 256>>>(query, key, value, n4_act);
    transpose_wqkv_kernel<<<dim3(kDH / 32, kD / 32, 3 * kH), dim3(32, 8)>>>(Wq, Wk, Wv);
    transpose_wo_kernel<<<dim3(kD / 32, kD / 32), dim3(32, 8)>>>(Wo);

    proj_mma_kernel<<<dim3(kS / 128, 3 * kH, kB), 256, GEMM_SMEM>>>(bq, bk, bvp);

    attn_mma_kernel<<<dim3(kS / 128, kH, kB), 256, ATTN_SMEM>>>(kmask);

    outproj_mma_kernel<<<dim3((kS * kB) / 128, kD / 64), 256, GEMM_SMEM>>>(bo, out);
}

// round 9
// speedup vs baseline: 2.9083x; 1.1123x over previous
#include <cuda_runtime.h>
#include <cuda_bf16.h>
#include <math.h>
#include <cstdint>

#define kS  1024
#define kB  4
#define kD  1024
#define kH  16
#define kDH 64

// bf16 split scratch (hi + residual-lo)
__device__ __nv_bfloat16 g_qa_hi[kS*kB*kD], g_qa_lo[kS*kB*kD];   // activations
__device__ __nv_bfloat16 g_ka_hi[kS*kB*kD], g_ka_lo[kS*kB*kD];
__device__ __nv_bfloat16 g_va_hi[kS*kB*kD], g_va_lo[kS*kB*kD];
__device__ __nv_bfloat16 g_oa_hi[kS*kB*kD], g_oa_lo[kS*kB*kD];   // attn out (concat)
__device__ __nv_bfloat16 g_wq_hi[kH*kDH*kD], g_wq_lo[kH*kDH*kD]; // [h][n][k]
__device__ __nv_bfloat16 g_wk_hi[kH*kDH*kD], g_wk_lo[kH*kDH*kD];
__device__ __nv_bfloat16 g_wv_hi[kH*kDH*kD], g_wv_lo[kH*kDH*kD];
__device__ __nv_bfloat16 g_wo_hi[kD*kD],     g_wo_lo[kD*kD];     // [n][k]
// projected q/k/v in bf16 split
__device__ __nv_bfloat16 g_qp_hi[kB*kH*kS*kDH], g_qp_lo[kB*kH*kS*kDH]; // [b][h][s][dh]
__device__ __nv_bfloat16 g_kp_hi[kB*kH*kS*kDH], g_kp_lo[kB*kH*kS*kDH]; // [b][h][s][dh]
__device__ __nv_bfloat16 g_vp_hi[kB*kH*kS*kDH], g_vp_lo[kB*kH*kS*kDH]; // [b][h][dh][s]

// ===================== helpers =====================
__device__ __forceinline__ uint32_t smem_u32(const void* p) {
    uint32_t a;
    asm("{ .reg .u64 t; cvta.to.shared.u64 t, %1; cvt.u32.u64 %0, t; }" : "=r"(a) : "l"(p));
    return a;
}
__device__ __forceinline__ void ldmatrix_x4(uint32_t* r, uint32_t a) {
    asm volatile("ldmatrix.sync.aligned.m8n8.x4.shared.b16 {%0,%1,%2,%3}, [%4];"
        : "=r"(r[0]), "=r"(r[1]), "=r"(r[2]), "=r"(r[3]) : "r"(a));
}
__device__ __forceinline__ void mma_bf16(float* c, const uint32_t* a, const uint32_t* b) {
    asm volatile("mma.sync.aligned.m16n8k16.row.col.f32.bf16.bf16.f32 "
        "{%0,%1,%2,%3},{%4,%5,%6,%7},{%8,%9},{%0,%1,%2,%3};"
        : "+f"(c[0]), "+f"(c[1]), "+f"(c[2]), "+f"(c[3])
        : "r"(a[0]), "r"(a[1]), "r"(a[2]), "r"(a[3]), "r"(b[0]), "r"(b[1]));
}
__device__ __forceinline__ void split_pack(float x, float y, uint32_t& hp, uint32_t& lp) {
    __nv_bfloat16 hx = __float2bfloat16_rn(x);
    __nv_bfloat16 hy = __float2bfloat16_rn(y);
    __nv_bfloat16 lx = __float2bfloat16_rn(x - __bfloat162float(hx));
    __nv_bfloat16 ly = __float2bfloat16_rn(y - __bfloat162float(hy));
    hp = (uint32_t)__bfloat16_as_ushort(hx) | ((uint32_t)__bfloat16_as_ushort(hy) << 16);
    lp = (uint32_t)__bfloat16_as_ushort(lx) | ((uint32_t)__bfloat16_as_ushort(ly) << 16);
}
__device__ __forceinline__ void cp_async16(uint32_t saddr, const void* gptr) {
    asm volatile("cp.async.cg.shared.global [%0], [%1], 16;" :: "r"(saddr), "l"(gptr));
}
#define CP_COMMIT() asm volatile("cp.async.commit_group;" ::: "memory")
#define CP_WAIT_1() asm volatile("cp.async.wait_group 1;" ::: "memory")
#define CP_WAIT_0() asm volatile("cp.async.wait_group 0;" ::: "memory")

// swizzled offset within a 128B-row tile: row-major, seg XOR (row&7)
__device__ __forceinline__ uint32_t sw_off(int row, int seg) {
    return (uint32_t)(row * 128 + ((seg ^ (row & 7)) << 4));
}

// ===========================================================================
// Prep 1: split q/k/v activations in one launch. grid (n4/256, 3)
// ===========================================================================
__global__ void __launch_bounds__(256) split3_kernel(
    const float* __restrict__ q, const float* __restrict__ k,
    const float* __restrict__ v, int n4)
{
    int which = blockIdx.y;
    const float* src = (which == 0) ? q : (which == 1) ? k : v;
    __nv_bfloat16* hi = (which == 0) ? g_qa_hi : (which == 1) ? g_ka_hi : g_va_hi;
    __nv_bfloat16* lo = (which == 0) ? g_qa_lo : (which == 1) ? g_ka_lo : g_va_lo;
    int i = blockIdx.x * blockDim.x + threadIdx.x;
    if (i >= n4) return;
    float4 vv = ((const float4*)src)[i];
    uint32_t h0, l0, h1, l1;
    split_pack(vv.x, vv.y, h0, l0);
    split_pack(vv.z, vv.w, h1, l1);
    *(uint2*)(hi + (size_t)i * 4) = make_uint2(h0, h1);
    *(uint2*)(lo + (size_t)i * 4) = make_uint2(l0, l1);
}

// ===========================================================================
// Prep 2: transpose+split weights
// ===========================================================================
__global__ void __launch_bounds__(256) transpose_wqkv_kernel(
    const float* __restrict__ Wq, const float* __restrict__ Wk,
    const float* __restrict__ Wv)
{
    __shared__ float tile[32][33];
    int which = blockIdx.z >> 4;
    int h = blockIdx.z & 15;
    const float* src = ((which == 0) ? Wq : (which == 1) ? Wk : Wv) + (size_t)h * kD * kDH;
    __nv_bfloat16* hi = ((which == 0) ? g_wq_hi : (which == 1) ? g_wk_hi : g_wv_hi) + (size_t)h * kDH * kD;
    __nv_bfloat16* lo = ((which == 0) ? g_wq_lo : (which == 1) ? g_wk_lo : g_wv_lo) + (size_t)h * kDH * kD;
    int c0 = blockIdx.x * 32, r0 = blockIdx.y * 32;
    int tx = threadIdx.x, ty = threadIdx.y;
    #pragma unroll
    for (int i = 0; i < 4; i++)
        tile[ty + i * 8][tx] = src[(size_t)(r0 + ty + i * 8) * kDH + c0 + tx];
    __syncthreads();
    #pragma unroll
    for (int i = 0; i < 4; i++) {
        float v = tile[tx][ty + i * 8];
        __nv_bfloat16 hv = __float2bfloat16_rn(v);
        __nv_bfloat16 lv = __float2bfloat16_rn(v - __bfloat162float(hv));
        size_t o = (size_t)(c0 + ty + i * 8) * kD + r0 + tx;
        hi[o] = hv;
        lo[o] = lv;
    }
}

__global__ void __launch_bounds__(256) transpose_wo_kernel(const float* __restrict__ Wo)
{
    __shared__ float tile[32][33];
    int c0 = blockIdx.x * 32, r0 = blockIdx.y * 32;
    int tx = threadIdx.x, ty = threadIdx.y;
    #pragma unroll
    for (int i = 0; i < 4; i++)
        tile[ty + i * 8][tx] = Wo[(size_t)(r0 + ty + i * 8) * kD + c0 + tx];
    __syncthreads();
    #pragma unroll
    for (int i = 0; i < 4; i++) {
        float v = tile[tx][ty + i * 8];
        __nv_bfloat16 hv = __float2bfloat16_rn(v);
        __nv_bfloat16 lv = __float2bfloat16_rn(v - __bfloat162float(hv));
        size_t o = (size_t)(c0 + ty + i * 8) * kD + r0 + tx;
        g_wo_hi[o] = hv;
        g_wo_lo[o] = lv;
    }
}

// ===========================================================================
// mma.sync GEMM, 2-stage cp.async pipeline, XOR-swizzled smem (no padding).
// BM=128, BN=64, BK=64, 256 thr. Stage: A_hi 0, A_lo 16384, B_hi 32768,
// B_lo 40960; stage size 49152. Two stages = 96KB -> 2 CTAs/SM.
// ===========================================================================
#define SA0 0
#define SA1 16384
#define SB0 32768
#define SB1 40960
#define STG_SZ 49152
#define GEMM_SMEM (2 * STG_SZ)   // 98304

__device__ __forceinline__ void gemm_compute_chunk(
    uint32_t stb, int wm, int wn, int lane, float acc[2][4][4])
{
    int lrow = lane & 15;
    int lseg = lane >> 4;
    #pragma unroll
    for (int ks = 0; ks < 4; ks++) {
        int seg = ks * 2 + lseg;
        uint32_t a0f[2][4], a1f[2][4], b0f[4][2], b1f[4][2];
        #pragma unroll
        for (int mt = 0; mt < 2; mt++) {
            uint32_t addr = stb + SA0 + sw_off(wm * 32 + mt * 16 + lrow, seg);
            ldmatrix_x4(a0f[mt], addr);
            ldmatrix_x4(a1f[mt], addr + (SA1 - SA0));
        }
        #pragma unroll
        for (int nt2 = 0; nt2 < 2; nt2++) {
            uint32_t addr = stb + SB0 + sw_off(wn * 32 + nt2 * 16 + lrow, seg);
            uint32_t t[4];
            ldmatrix_x4(t, addr);
            b0f[nt2 * 2 + 0][0] = t[0]; b0f[nt2 * 2 + 0][1] = t[2];
            b0f[nt2 * 2 + 1][0] = t[1]; b0f[nt2 * 2 + 1][1] = t[3];
            ldmatrix_x4(t, addr + (SB1 - SB0));
            b1f[nt2 * 2 + 0][0] = t[0]; b1f[nt2 * 2 + 0][1] = t[2];
            b1f[nt2 * 2 + 1][0] = t[1]; b1f[nt2 * 2 + 1][1] = t[3];
        }
        #pragma unroll
        for (int mt = 0; mt < 2; mt++)
            #pragma unroll
            for (int nt = 0; nt < 4; nt++) {
                mma_bf16(acc[mt][nt], a0f[mt], b0f[nt]);
                mma_bf16(acc[mt][nt], a0f[mt], b1f[nt]);
                mma_bf16(acc[mt][nt], a1f[mt], b0f[nt]);
            }
    }
}

// ---- fused projections. grid (8, 48, 4): y -> which*16+h ----
__global__ void __launch_bounds__(256) proj_mma_kernel(
    const float* __restrict__ bq, const float* __restrict__ bk,
    const float* __restrict__ bv)
{
    extern __shared__ char smem[];
    uint32_t sbase = smem_u32(smem);
    int s0 = blockIdx.x * 128;
    int which = blockIdx.y >> 4;
    int h  = blockIdx.y & 15;
    int b  = blockIdx.z;
    int tid = threadIdx.x;
    int wid = tid >> 5, lane = tid & 31;
    int wm = wid >> 1, wn = wid & 1;

    const __nv_bfloat16* a_hi = (which == 0) ? g_qa_hi : (which == 1) ? g_ka_hi : g_va_hi;
    const __nv_bfloat16* a_lo = (which == 0) ? g_qa_lo : (which == 1) ? g_ka_lo : g_va_lo;
    const __nv_bfloat16* w_hi = (which == 0) ? g_wq_hi : (which == 1) ? g_wk_hi : g_wv_hi;
    const __nv_bfloat16* w_lo = (which == 0) ? g_wq_lo : (which == 1) ? g_wk_lo : g_wv_lo;
    const float* bias = (which == 0) ? bq : (which == 1) ? bk : bv;

    float acc[2][4][4];
    #pragma unroll
    for (int mt = 0; mt < 2; mt++)
        #pragma unroll
        for (int nt = 0; nt < 4; nt++)
            #pragma unroll
            for (int e = 0; e < 4; e++) acc[mt][nt][e] = 0.f;

    auto load_chunk = [&](int c, int stg) {
        uint32_t stb = sbase + stg * STG_SZ;
        int k0 = c * 64;
        #pragma unroll
        for (int i = 0; i < 4; i++) {
            int id = tid + i * 256;
            int m = id >> 3, k8 = id & 7;
            size_t g = ((size_t)(s0 + m) * kB + b) * kD + k0 + k8 * 8;
            uint32_t d = stb + sw_off(m, k8);
            cp_async16(d + SA0, a_hi + g);
            cp_async16(d + SA1, a_lo + g);
        }
        #pragma unroll
        for (int i = 0; i < 2; i++) {
            int id = tid + i * 256;
            int n = id >> 3, k8 = id & 7;
            size_t g = ((size_t)h * kDH + n) * kD + k0 + k8 * 8;
            uint32_t d = stb + sw_off(n, k8);
            cp_async16(d + SB0, w_hi + g);
            cp_async16(d + SB1, w_lo + g);
        }
    };

    load_chunk(0, 0);
    CP_COMMIT();
    for (int c = 0; c < 16; c++) {
        if (c < 15) {
            load_chunk(c + 1, (c + 1) & 1);
            CP_COMMIT();
            CP_WAIT_1();
        } else {
            CP_WAIT_0();
        }
        __syncthreads();
        gemm_compute_chunk(sbase + (c & 1) * STG_SZ, wm, wn, lane, acc);
        __syncthreads();
    }

    int gq = lane >> 2, tg = lane & 3;
    size_t bh = (size_t)b * kH + h;
    if (which < 2) {
        __nv_bfloat16* oh = (which == 0) ? g_qp_hi : g_kp_hi;
        __nv_bfloat16* ol = (which == 0) ? g_qp_lo : g_kp_lo;
        #pragma unroll
        for (int mt = 0; mt < 2; mt++) {
            int row0 = s0 + wm * 32 + mt * 16 + gq;
            #pragma unroll
            for (int nt = 0; nt < 4; nt++) {
                int col = wn * 32 + nt * 8 + tg * 2;
                float b0 = bias[h * kDH + col], b1 = bias[h * kDH + col + 1];
                uint32_t hp, lp;
                size_t off0 = (bh * kS + row0) * kDH + col;
                split_pack(acc[mt][nt][0] + b0, acc[mt][nt][1] + b1, hp, lp);
                *(uint32_t*)(oh + off0) = hp; *(uint32_t*)(ol + off0) = lp;
                split_pack(acc[mt][nt][2] + b0, acc[mt][nt][3] + b1, hp, lp);
                size_t off1 = off0 + (size_t)8 * kDH;
                *(uint32_t*)(oh + off1) = hp; *(uint32_t*)(ol + off1) = lp;
            }
        }
    } else {
        #pragma unroll
        for (int mt = 0; mt < 2; mt++) {
            int row0 = s0 + wm * 32 + mt * 16 + gq;
            #pragma unroll
            for (int nt = 0; nt < 4; nt++) {
                int col = wn * 32 + nt * 8 + tg * 2;
                float b0 = bias[h * kDH + col], b1 = bias[h * kDH + col + 1];
                float vals[4] = {acc[mt][nt][0] + b0, acc[mt][nt][1] + b1,
                                 acc[mt][nt][2] + b0, acc[mt][nt][3] + b1};
                int rr[4] = {row0, row0, row0 + 8, row0 + 8};
                int cc[4] = {col, col + 1, col, col + 1};
                #pragma unroll
                for (int e = 0; e < 4; e++) {
                    __nv_bfloat16 hv = __float2bfloat16_rn(vals[e]);
                    __nv_bfloat16 lv = __float2bfloat16_rn(vals[e] - __bfloat162float(hv));
                    size_t off = (bh * kDH + cc[e]) * kS + rr[e];
                    g_vp_hi[off] = hv;
                    g_vp_lo[off] = lv;
                }
            }
        }
    }
}

// ---- output projection ----
__global__ void __launch_bounds__(256) outproj_mma_kernel(
    const float* __restrict__ bo, float* __restrict__ out)
{
    extern __shared__ char smem[];
    uint32_t sbase = smem_u32(smem);
    int m0 = blockIdx.x * 128;
    int n0 = blockIdx.y * 64;
    int tid = threadIdx.x;
    int wid = tid >> 5, lane = tid & 31;
    int wm = wid >> 1, wn = wid & 1;

    float acc[2][4][4];
    #pragma unroll
    for (int mt = 0; mt < 2; mt++)
        #pragma unroll
        for (int nt = 0; nt < 4; nt++)
            #pragma unroll
            for (int e = 0; e < 4; e++) acc[mt][nt][e] = 0.f;

    auto load_chunk = [&](int c, int stg) {
        uint32_t stb = sbase + stg * STG_SZ;
        int k0 = c * 64;
        #pragma unroll
        for (int i = 0; i < 4; i++) {
            int id = tid + i * 256;
            int m = id >> 3, k8 = id & 7;
            size_t g = (size_t)(m0 + m) * kD + k0 + k8 * 8;
            uint32_t d = stb + sw_off(m, k8);
            cp_async16(d + SA0, g_oa_hi + g);
            cp_async16(d + SA1, g_oa_lo + g);
        }
        #pragma unroll
        for (int i = 0; i < 2; i++) {
            int id = tid + i * 256;
            int n = id >> 3, k8 = id & 7;
            size_t g = (size_t)(n0 + n) * kD + k0 + k8 * 8;
            uint32_t d = stb + sw_off(n, k8);
            cp_async16(d + SB0, g_wo_hi + g);
            cp_async16(d + SB1, g_wo_lo + g);
        }
    };

    load_chunk(0, 0);
    CP_COMMIT();
    for (int c = 0; c < 16; c++) {
        if (c < 15) {
            load_chunk(c + 1, (c + 1) & 1);
            CP_COMMIT();
            CP_WAIT_1();
        } else {
            CP_WAIT_0();
        }
        __syncthreads();
        gemm_compute_chunk(sbase + (c & 1) * STG_SZ, wm, wn, lane, acc);
        __syncthreads();
    }

    int gq = lane >> 2, tg = lane & 3;
    #pragma unroll
    for (int mt = 0; mt < 2; mt++) {
        int row = m0 + wm * 32 + mt * 16 + gq;
        #pragma unroll
        for (int nt = 0; nt < 4; nt++) {
            int col = n0 + wn * 32 + nt * 8 + tg * 2;
            float b0 = bo[col], b1 = bo[col + 1];
            size_t r0 = (size_t)row * kD + col;
            *(float2*)(out + r0) = make_float2(acc[mt][nt][0] + b0, acc[mt][nt][1] + b1);
            *(float2*)(out + r0 + 8 * kD) = make_float2(acc[mt][nt][2] + b0, acc[mt][nt][3] + b1);
        }
    }
}

// ===========================================================================
// Tensor-core attention, swizzled smem, 2-stage cp.async K/V pipeline.
// Stage: K_hi 0, K_lo 8192, V_hi 16384, V_lo 24576; stage 32768.
// Mask at 65536 (4KB). Total 69632 -> 3 CTAs/SM.
// ===========================================================================
#define AK_HI 0
#define AK_LO 8192
#define AV_HI 16384
#define AV_LO 24576
#define ASTG  32768
#define AMK   65536
#define ATTN_SMEM (65536 + 4096)

__global__ void __launch_bounds__(256) attn_mma_kernel(const int* __restrict__ mask)
{
    extern __shared__ char smem[];
    uint32_t sbase = smem_u32(smem);
    int s0 = blockIdx.x * 128;
    int h  = blockIdx.y;
    int b  = blockIdx.z;
    int tid = threadIdx.x;
    int w = tid >> 5, lane = tid & 31;
    int gq = lane >> 2, tg = lane & 3;
    size_t bh = (size_t)b * kH + h;

    const __nv_bfloat16* qh = g_qp_hi + bh * kS * kDH;
    const __nv_bfloat16* ql = g_qp_lo + bh * kS * kDH;
    const __nv_bfloat16* kh = g_kp_hi + bh * kS * kDH;
    const __nv_bfloat16* kl = g_kp_lo + bh * kS * kDH;
    const __nv_bfloat16* vth = g_vp_hi + bh * kDH * kS;  // [dh][s]
    const __nv_bfloat16* vtl = g_vp_lo + bh * kDH * kS;

    // ---- mask preload ----
    float* Mk = (float*)(smem + AMK);
    for (int idx = tid; idx < kS; idx += 256)
        Mk[idx] = (float)mask[(size_t)idx * kB + b] * 1e18f;

    // ---- stage Q tile (128 rows hi at 0, lo at 16384; swizzled) ----
    #pragma unroll
    for (int i = 0; i < 4; i++) {
        int id = tid + i * 256;
        int row = id >> 3, k8 = id & 7;
        size_t g = (size_t)(s0 + row) * kDH + k8 * 8;
        uint32_t d = sbase + sw_off(row, k8);
        cp_async16(d, qh + g);
        cp_async16(d + 16384, ql + g);
    }
    CP_COMMIT();
    CP_WAIT_0();
    __syncthreads();
    uint32_t qfh[4][4], qfl[4][4];
    {
        int lrow = lane & 15, lseg = lane >> 4;
        #pragma unroll
        for (int ks = 0; ks < 4; ks++) {
            uint32_t addr = sbase + sw_off(w * 16 + lrow, ks * 2 + lseg);
            ldmatrix_x4(qfh[ks], addr);
            ldmatrix_x4(qfl[ks], addr + 16384);
        }
    }
    __syncthreads();  // Q reads done before stage reuse

    float acc_o[8][4];
    #pragma unroll
    for (int nt = 0; nt < 8; nt++)
        #pragma unroll
        for (int e = 0; e < 4; e++) acc_o[nt][e] = 0.f;
    float l_run[2] = {0.f, 0.f};
    const float scale = 0.125f;

    auto load_tile = [&](int t, int stg) {
        uint32_t stb = sbase + stg * ASTG;
        int j0 = t * 64;
        #pragma unroll
        for (int i = 0; i < 8; i++) {
            int id = tid + (i & 1) * 256;
            int row = id >> 3, k8 = id & 7;
            const __nv_bfloat16* src;
            uint32_t dst;
            if (i < 2)      { src = kh  + (size_t)(j0 + row) * kDH + k8 * 8; dst = AK_HI; }
            else if (i < 4) { src = kl  + (size_t)(j0 + row) * kDH + k8 * 8; dst = AK_LO; }
            else if (i < 6) { src = vth + (size_t)row * kS + j0 + k8 * 8;    dst = AV_HI; }
            else            { src = vtl + (size_t)row * kS + j0 + k8 * 8;    dst = AV_LO; }
            cp_async16(stb + dst + sw_off(row, k8), src);
        }
    };

    load_tile(0, 0);
    CP_COMMIT();
    int lrow = lane & 15, lseg = lane >> 4;
    for (int t = 0; t < 16; t++) {
        if (t < 15) {
            load_tile(t + 1, (t + 1) & 1);
            CP_COMMIT();
            CP_WAIT_1();
        } else {
            CP_WAIT_0();
        }
        __syncthreads();
        uint32_t stb = sbase + (t & 1) * ASTG;
        int j0 = t * 64;

        // ---- S = Q K^T (3-pass) ----
        float ps[8][4];
        #pragma unroll
        for (int nt = 0; nt < 8; nt++)
            #pragma unroll
            for (int e = 0; e < 4; e++) ps[nt][e] = 0.f;
        #pragma unroll
        for (int ks = 0; ks < 4; ks++) {
            int seg = ks * 2 + lseg;
            #pragma unroll
            for (int nt2 = 0; nt2 < 4; nt2++) {
                uint32_t addr = stb + AK_HI + sw_off(nt2 * 16 + lrow, seg);
                uint32_t tt[4], u[4];
                ldmatrix_x4(tt, addr);
                ldmatrix_x4(u, addr + (AK_LO - AK_HI));
                uint32_t bh0[2] = {tt[0], tt[2]}, bh1[2] = {tt[1], tt[3]};
                uint32_t bl0[2] = {u[0], u[2]}, bl1[2] = {u[1], u[3]};
                mma_bf16(ps[nt2 * 2 + 0], qfh[ks], bh0);
                mma_bf16(ps[nt2 * 2 + 0], qfh[ks], bl0);
                mma_bf16(ps[nt2 * 2 + 0], qfl[ks], bh0);
                mma_bf16(ps[nt2 * 2 + 1], qfh[ks], bh1);
                mma_bf16(ps[nt2 * 2 + 1], qfh[ks], bl1);
                mma_bf16(ps[nt2 * 2 + 1], qfl[ks], bh1);
            }
        }

        // ---- softmax weights ----
        float l0 = 0.f, l1 = 0.f;
        #pragma unroll
        for (int nt = 0; nt < 8; nt++) {
            float mk0 = Mk[j0 + nt * 8 + tg * 2], mk1 = Mk[j0 + nt * 8 + tg * 2 + 1];
            float p0 = __expf(fminf(ps[nt][0] * scale - mk0, 60.f));
            float p1 = __expf(fminf(ps[nt][1] * scale - mk1, 60.f));
            float p2 = __expf(fminf(ps[nt][2] * scale - mk0, 60.f));
            float p3 = __expf(fminf(ps[nt][3] * scale - mk1, 60.f));
            l0 += p0 + p1; l1 += p2 + p3;
            ps[nt][0] = p0; ps[nt][1] = p1; ps[nt][2] = p2; ps[nt][3] = p3;
        }
        l_run[0] += l0; l_run[1] += l1;

        // ---- O += P V (P split in regs, 3-pass) ----
        #pragma unroll
        for (int ks = 0; ks < 4; ks++) {
            uint32_t pah[4], pal[4];
            split_pack(ps[2 * ks + 0][0], ps[2 * ks + 0][1], pah[0], pal[0]);
            split_pack(ps[2 * ks + 0][2], ps[2 * ks + 0][3], pah[1], pal[1]);
            split_pack(ps[2 * ks + 1][0], ps[2 * ks + 1][1], pah[2], pal[2]);
            split_pack(ps[2 * ks + 1][2], ps[2 * ks + 1][3], pah[3], pal[3]);
            int seg = ks * 2 + lseg;
            #pragma unroll
            for (int nd2 = 0; nd2 < 4; nd2++) {
                uint32_t addr = stb + AV_HI + sw_off(nd2 * 16 + lrow, seg);
                uint32_t tt[4], u[4];
                ldmatrix_x4(tt, addr);
                ldmatrix_x4(u, addr + (AV_LO - AV_HI));
                uint32_t bh0[2] = {tt[0], tt[2]}, bh1[2] = {tt[1], tt[3]};
                uint32_t bl0[2] = {u[0], u[2]}, bl1[2] = {u[1], u[3]};
                mma_bf16(acc_o[nd2 * 2 + 0], pah, bh0);
                mma_bf16(acc_o[nd2 * 2 + 0], pah, bl0);
                mma_bf16(acc_o[nd2 * 2 + 0], pal, bh0);
                mma_bf16(acc_o[nd2 * 2 + 1], pah, bh1);
                mma_bf16(acc_o[nd2 * 2 + 1], pah, bl1);
                mma_bf16(acc_o[nd2 * 2 + 1], pal, bh1);
            }
        }
        __syncthreads();
    }

    // ---- normalize and write bf16-split concat output ----
    #pragma unroll
    for (int off = 1; off <= 2; off <<= 1) {
        l_run[0] += __shfl_xor_sync(0xffffffffu, l_run[0], off);
        l_run[1] += __shfl_xor_sync(0xffffffffu, l_run[1], off);
    }
    float inv0 = 1.0f / l_run[0], inv1 = 1.0f / l_run[1];

    int srow = s0 + w * 16 + gq;
    size_t m0r = ((size_t)srow * kB + b) * kD + (size_t)h * kDH;
    size_t m1r = ((size_t)(srow + 8) * kB + b) * kD + (size_t)h * kDH;
    #pragma unroll
    for (int nt = 0; nt < 8; nt++) {
        int col = nt * 8 + tg * 2;
        uint32_t hp, lp;
        split_pack(acc_o[nt][0] * inv0, acc_o[nt][1] * inv0, hp, lp);
        *(uint32_t*)(g_oa_hi + m0r + col) = hp;
        *(uint32_t*)(g_oa_lo + m0r + col) = lp;
        split_pack(acc_o[nt][2] * inv1, acc_o[nt][3] * inv1, hp, lp);
        *(uint32_t*)(g_oa_hi + m1r + col) = hp;
        *(uint32_t*)(g_oa_lo + m1r + col) = lp;
    }
}

// ---------------------------------------------------------------------------
extern "C" void kernel_launch(void* const* d_in, const int* in_sizes, int n_in,
                              void* d_out, int out_size) {
    (void)in_sizes; (void)n_in; (void)out_size;
    const float* query = (const float*)d_in[0];
    const float* key   = (const float*)d_in[1];
    const float* value = (const float*)d_in[2];
    const int*   kmask = (const int*)  d_in[3];
    const float* Wq    = (const float*)d_in[4];
    const float* bq    = (const float*)d_in[5];
    const float* Wk    = (const float*)d_in[6];
    const float* bk    = (const float*)d_in[7];
    const float* Wv    = (const float*)d_in[8];
    const float* bvp   = (const float*)d_in[9];
    const float* Wo    = (const float*)d_in[10];
    const float* bo    = (const float*)d_in[11];
    float* out = (float*)d_out;

    cudaFuncSetAttribute(proj_mma_kernel, cudaFuncAttributeMaxDynamicSharedMemorySize, GEMM_SMEM);
    cudaFuncSetAttribute(outproj_mma_kernel, cudaFuncAttributeMaxDynamicSharedMemorySize, GEMM_SMEM);
    cudaFuncSetAttribute(attn_mma_kernel, cudaFuncAttributeMaxDynamicSharedMemorySize, ATTN_SMEM);

    const int n4_act = kS * kB * kD / 4;

    split3_kernel<<<dim3(n4_act / 256, 3), 256>>>(query, key, value, n4_act);
    transpose_wqkv_kernel<<<dim3(kDH / 32, kD / 32, 3 * kH), dim3(32, 8)>>>(Wq, Wk, Wv);
    transpose_wo_kernel<<<dim3(kD / 32, kD / 32), dim3(32, 8)>>>(Wo);

    proj_mma_kernel<<<dim3(kS / 128, 3 * kH, kB), 256, GEMM_SMEM>>>(bq, bk, bvp);

    attn_mma_kernel<<<dim3(kS / 128, kH, kB), 256, ATTN_SMEM>>>(kmask);

    outproj_mma_kernel<<<dim3((kS * kB) / 128, kD / 64), 256, GEMM_SMEM>>>(bo, out);
}